// round 11
// baseline (speedup 1.0000x reference)
#include <cuda_runtime.h>
#include <cuda_fp16.h>
#include <cstddef>
#include <cstdint>

#define DIMC   384
#define HEADS  12
#define HD     32
#define NTOK   256
#define BATCH  256
#define BHTOT  (BATCH * HEADS)      // 3072
#define MTOT   (BATCH * NTOK)       // 65536
#define KWIN   5
#define EPS    1e-6f
#define KEXT   (2 * DIMC)           // 768: A=[hi|lo], W=[hi|hi] (fp16 split)

// ---------------- scratch (device globals: allocation-free) ----------------
__device__ float g_q[(size_t)BHTOT * NTOK * HD];
__device__ float g_k[(size_t)BHTOT * NTOK * HD];
__device__ float g_v[(size_t)BHTOT * NTOK * HD];

__device__ __half g_ae[(size_t)MTOT * KEXT];       // y_ext (proj GEMM input)
__device__ __half g_we[(size_t)(3 * DIMC) * KEXT]; // qkv_w extended
__device__ __half g_pe[(size_t)DIMC * KEXT];       // proj_w extended

// ---------------- PTX helpers ----------------------------------------------
#define LDSM_X4(r0, r1, r2, r3, addr) \
    asm volatile("ldmatrix.sync.aligned.m8n8.x4.shared.b16 {%0,%1,%2,%3}, [%4];" \
        : "=r"(r0), "=r"(r1), "=r"(r2), "=r"(r3) : "r"(addr))

#define MMA_F16(c, a, b0, b1) \
    asm volatile("mma.sync.aligned.m16n8k16.row.col.f32.f16.f16.f32 " \
        "{%0,%1,%2,%3}, {%4,%5,%6,%7}, {%8,%9}, {%0,%1,%2,%3};" \
        : "+f"(c[0]), "+f"(c[1]), "+f"(c[2]), "+f"(c[3]) \
        : "r"(a[0]), "r"(a[1]), "r"(a[2]), "r"(a[3]), "r"(b0), "r"(b1))

// ---------------- fp32 -> fp16 [hi|hi] weight conversion --------------------
__global__ void __launch_bounds__(256) cvt_W_ext(
    const float* __restrict__ src, __half* __restrict__ dst, int nquads)
{
    int i = blockIdx.x * blockDim.x + threadIdx.x;
    if (i >= nquads) return;
    float4 v = *(const float4*)&src[(size_t)i * 4];
    int row = (i * 4) / DIMC;
    int k   = (i * 4) % DIMC;
    __half h[4];
    float vv[4] = {v.x, v.y, v.z, v.w};
#pragma unroll
    for (int j = 0; j < 4; j++) h[j] = __float2half(vv[j]);
    size_t base = (size_t)row * KEXT;
    uint2 hp;
    ((__half*)&hp)[0] = h[0]; ((__half*)&hp)[1] = h[1];
    ((__half*)&hp)[2] = h[2]; ((__half*)&hp)[3] = h[3];
    *(uint2*)&dst[base + k]        = hp;
    *(uint2*)&dst[base + DIMC + k] = hp;
}

// ---------------- fp16 tensor-core GEMM -------------------------------------
// C[m][n] = sum_k' Aext[m][k'] * Wext[n][k'], k' = 768. BM=BN=128, BK=32.
// 8 warps: warp grid 2(m) x 4(n), warp tile 64x32, mma m16n8k16.
// FUSE=1 (EPI=0): A loaded as fp32 x, converted hi/lo on the fly (k-tiles
// 0..11 = hi segment, 12..23 = lo segment).
#define BKB 32
#define APITCH 40   // 32 + 8 pad (fp16) -> 80B row, conflict-free LDSM

template <int EPI>
__global__ void __launch_bounds__(256, 2) gemm_f16(
    const __half* __restrict__ Aext, const float* __restrict__ Araw,
    const __half* __restrict__ Wext,
    const float* __restrict__ bias, const float* __restrict__ pos_enc,
    float* __restrict__ Cout)
{
    __shared__ __half As[2][128][APITCH];
    __shared__ __half Bs[2][128][APITCH];

    const int tid  = threadIdx.x;
    const int lane = tid & 31;
    const int warp = tid >> 5;
    const int wm = warp >> 2;      // 0..1
    const int wn = warp & 3;       // 0..3
    const int bm = blockIdx.y * 128;
    const int bn = blockIdx.x * 128;

    int lrow[2], lch[2];
#pragma unroll
    for (int l = 0; l < 2; l++) {
        int idx = tid + l * 256;
        lrow[l] = idx >> 2;
        lch[l] = idx & 3;
    }

    // A-tile fragment loader: EPI=0 converts fp32 x -> fp16 hi/lo on the fly.
    auto loadA = [&](int kt, int l) -> int4 {
        if (EPI == 0) {
            int seg = kt / 12;
            int kc  = (kt - seg * 12) * 32 + lch[l] * 8;
            const float* src = Araw + (size_t)(bm + lrow[l]) * DIMC + kc;
            float4 xa = *(const float4*)src;
            float4 xb = *(const float4*)(src + 4);
            float v[8] = {xa.x, xa.y, xa.z, xa.w, xb.x, xb.y, xb.z, xb.w};
            union { int4 i4; __half h[8]; } u;
#pragma unroll
            for (int j = 0; j < 8; j++) {
                __half hi = __float2half(v[j]);
                u.h[j] = seg ? __float2half(v[j] - __half2float(hi)) : hi;
            }
            return u.i4;
        } else {
            return *(const int4*)&Aext[(size_t)(bm + lrow[l]) * KEXT +
                                       kt * BKB + lch[l] * 8];
        }
    };

    float acc[4][4][4];
#pragma unroll
    for (int mt = 0; mt < 4; mt++)
#pragma unroll
        for (int nt = 0; nt < 4; nt++)
#pragma unroll
            for (int e = 0; e < 4; e++) acc[mt][nt][e] = 0.f;

    int4 pa[2], pb[2];
#pragma unroll
    for (int l = 0; l < 2; l++) {
        pa[l] = loadA(0, l);
        pb[l] = *(const int4*)&Wext[(size_t)(bn + lrow[l]) * KEXT + lch[l] * 8];
    }
#pragma unroll
    for (int l = 0; l < 2; l++) {
        *(int4*)&As[0][lrow[l]][lch[l] * 8] = pa[l];
        *(int4*)&Bs[0][lrow[l]][lch[l] * 8] = pb[l];
    }
    __syncthreads();

    const int nkt = KEXT / BKB;   // 24
    for (int kt = 0; kt < nkt; kt++) {
        const int cur = kt & 1;
        const bool has_next = (kt + 1 < nkt);
        if (has_next) {
            int ko = (kt + 1) * BKB;
#pragma unroll
            for (int l = 0; l < 2; l++) {
                pa[l] = loadA(kt + 1, l);
                pb[l] = *(const int4*)&Wext[(size_t)(bn + lrow[l]) * KEXT + ko + lch[l] * 8];
            }
        }

#pragma unroll
        for (int s = 0; s < 2; s++) {       // two k16 steps
            uint32_t a[4][4];
#pragma unroll
            for (int mt = 0; mt < 4; mt++) {
                int r = wm * 64 + mt * 16 + (lane & 15);
                int c = s * 16 + ((lane >> 4) << 3);
                uint32_t ad = (uint32_t)__cvta_generic_to_shared(&As[cur][r][c]);
                LDSM_X4(a[mt][0], a[mt][1], a[mt][2], a[mt][3], ad);
            }
            uint32_t b[4][2];
#pragma unroll
            for (int nt2 = 0; nt2 < 2; nt2++) {
                int r = wn * 32 + nt2 * 16 + ((lane >> 4) << 3) + (lane & 7);
                int c = s * 16 + (((lane >> 3) & 1) << 3);
                uint32_t ad = (uint32_t)__cvta_generic_to_shared(&Bs[cur][r][c]);
                LDSM_X4(b[nt2 * 2][0], b[nt2 * 2][1],
                        b[nt2 * 2 + 1][0], b[nt2 * 2 + 1][1], ad);
            }
#pragma unroll
            for (int mt = 0; mt < 4; mt++)
#pragma unroll
                for (int nt = 0; nt < 4; nt++)
                    MMA_F16(acc[mt][nt], a[mt], b[nt][0], b[nt][1]);
        }

        if (has_next) {
            const int nxt = cur ^ 1;
#pragma unroll
            for (int l = 0; l < 2; l++) {
                *(int4*)&As[nxt][lrow[l]][lch[l] * 8] = pa[l];
                *(int4*)&Bs[nxt][lrow[l]][lch[l] * 8] = pb[l];
            }
        }
        __syncthreads();
    }

    // ---- epilogue ----
    if (EPI == 0) {
#pragma unroll
        for (int mt = 0; mt < 4; mt++) {
            int m0 = bm + wm * 64 + mt * 16 + (lane >> 2);
#pragma unroll
            for (int nt = 0; nt < 4; nt++) {
                int n0 = bn + wn * 32 + nt * 8 + (lane & 3) * 2;
#pragma unroll
                for (int e = 0; e < 4; e++) {
                    int m = m0 + (e >> 1) * 8;
                    int n = n0 + (e & 1);
                    int b = m >> 8;
                    int i = m & 255;
                    float val = acc[mt][nt][e] + bias[n];
                    int region = n / DIMC;
                    int ch = n - region * DIMC;
                    int h = ch >> 5;
                    int d = ch & 31;
                    size_t dst = ((size_t)(b * HEADS + h) * NTOK + i) * HD + d;
                    if (region == 0) {
                        g_q[dst] = fmaxf(val, 0.f);
                    } else if (region == 1) {
                        g_k[dst] = fmaxf(val + pos_enc[(size_t)i * DIMC + ch], 0.f);
                    } else {
                        g_v[dst] = val;
                    }
                }
            }
        }
    } else {
#pragma unroll
        for (int mt = 0; mt < 4; mt++) {
            int m0 = bm + wm * 64 + mt * 16 + (lane >> 2);
#pragma unroll
            for (int nt = 0; nt < 4; nt++) {
                int n0 = bn + wn * 32 + nt * 8 + (lane & 3) * 2;
                float2 lo, hi2;
                lo.x  = acc[mt][nt][0] + bias[n0];
                lo.y  = acc[mt][nt][1] + bias[n0 + 1];
                hi2.x = acc[mt][nt][2] + bias[n0];
                hi2.y = acc[mt][nt][3] + bias[n0 + 1];
                *(float2*)&Cout[(size_t)m0 * DIMC + n0] = lo;
                *(float2*)&Cout[(size_t)(m0 + 8) * DIMC + n0] = hi2;
            }
        }
    }
}

// ---------------- fused linear attention + depthwise conv (v2) -------------
// Transposed smem layouts: k_t, v_t are [d][j] (pitch 260) so the kv phase
// reads float4 along j. q is read straight from gmem per thread. 74.6 KB
// smem -> 2 CTAs/SM. Epilogue writes [hi|lo] fp16 ext row into g_ae.
#define TP     260                      // transposed pitch (floats, 4-aligned)
#define A2_VT  0                        // v_t: 32 x 260
#define A2_KT  (32 * TP)                // k_t: 32 x 260
#define A2_KV  (2 * 32 * TP)            // kv:  32 x 36
#define A2_KS  (A2_KV + 32 * 36)        // ksum: 32
#define A2_WT  (A2_KS + 32)             // ws_t: 25 x 32 = 800
#define A2_B   (A2_WT + 800)            // bias: 32
#define A2_FLOATS (A2_B + 32)           // 18656 floats
#define A2_BYTES  (A2_FLOATS * 4)       // 74624 bytes

__global__ void __launch_bounds__(256, 2) attn_kernel(
    const float* __restrict__ dwc_w, const float* __restrict__ dwc_b)
{
    extern __shared__ float sm[];
    float* vt   = sm + A2_VT;
    float* ktm  = sm + A2_KT;
    float* kvs  = sm + A2_KV;
    float* ksum = sm + A2_KS;
    float* wst  = sm + A2_WT;
    float* bsm  = sm + A2_B;

    const int tid = threadIdx.x;
    const int bh = blockIdx.x;
    const size_t base = (size_t)bh * (NTOK * HD);

    // load k, v transposed: [j][d] gmem -> [d][j] smem
    for (int idx = tid; idx < 2048; idx += 256) {
        int row = idx >> 3;            // j
        int col = (idx & 7) * 4;       // d base
        float4 t = *(const float4*)&g_k[base + row * 32 + col];
        ktm[(col + 0) * TP + row] = t.x;
        ktm[(col + 1) * TP + row] = t.y;
        ktm[(col + 2) * TP + row] = t.z;
        ktm[(col + 3) * TP + row] = t.w;
        t = *(const float4*)&g_v[base + row * 32 + col];
        vt[(col + 0) * TP + row] = t.x;
        vt[(col + 1) * TP + row] = t.y;
        vt[(col + 2) * TP + row] = t.z;
        vt[(col + 3) * TP + row] = t.w;
    }
    // conv weights transposed: ws_t[tap][d] = dwc_w[d*25 + tap]
    for (int idx = tid; idx < 800; idx += 256)
        wst[idx] = dwc_w[(idx & 31) * 25 + (idx >> 5)];
    if (tid < 32) bsm[tid] = dwc_b[tid];
    __syncthreads();

    // phase 1: kv[c][d] = sum_j k[j][c] v[j][d]; ksum[c] = sum_j k[j][c]
    {
        const int c  = tid >> 3;
        const int d0 = (tid & 7) * 4;
        float a0 = 0.f, a1 = 0.f, a2 = 0.f, a3 = 0.f, s = 0.f;
        for (int j = 0; j < 256; j += 4) {
            float4 kq = *(const float4*)&ktm[c * TP + j];
            float4 v0 = *(const float4*)&vt[(d0 + 0) * TP + j];
            float4 v1 = *(const float4*)&vt[(d0 + 1) * TP + j];
            float4 v2 = *(const float4*)&vt[(d0 + 2) * TP + j];
            float4 v3 = *(const float4*)&vt[(d0 + 3) * TP + j];
            a0 += kq.x * v0.x + kq.y * v0.y + kq.z * v0.z + kq.w * v0.w;
            a1 += kq.x * v1.x + kq.y * v1.y + kq.z * v1.z + kq.w * v1.w;
            a2 += kq.x * v2.x + kq.y * v2.y + kq.z * v2.z + kq.w * v2.w;
            a3 += kq.x * v3.x + kq.y * v3.y + kq.z * v3.z + kq.w * v3.w;
            s  += kq.x + kq.y + kq.z + kq.w;
        }
        float4 o; o.x = a0; o.y = a1; o.z = a2; o.w = a3;
        *(float4*)&kvs[c * 36 + d0] = o;
        if ((tid & 7) == 0) ksum[c] = s;
    }
    __syncthreads();

    // phase 2: out[i][d] = z_i * sum_c q[i][c] kv[c][d] + conv(v)[i][d] + b[d]
    const int i = tid;
    float qr[32];
#pragma unroll
    for (int j = 0; j < 8; j++)
        *(float4*)&qr[j * 4] = *(const float4*)&g_q[base + i * 32 + j * 4];

    float zden = EPS;
#pragma unroll
    for (int c = 0; c < 32; c++) zden += qr[c] * ksum[c];
    const float z = 1.0f / zden;

    float acc[32];
#pragma unroll
    for (int d = 0; d < 32; d++) acc[d] = 0.f;
#pragma unroll
    for (int c = 0; c < 32; c++) {
        float qc = qr[c];
#pragma unroll
        for (int dk = 0; dk < 8; dk++) {
            float4 kv4 = *(const float4*)&kvs[c * 36 + dk * 4];
            acc[dk * 4 + 0] += qc * kv4.x;
            acc[dk * 4 + 1] += qc * kv4.y;
            acc[dk * 4 + 2] += qc * kv4.z;
            acc[dk * 4 + 3] += qc * kv4.w;
        }
    }
#pragma unroll
    for (int d = 0; d < 32; d++) acc[d] *= z;

    // depthwise 5x5 conv via v_t[d][nn]
    const int a = i >> 4;
    const int b_s = i & 15;
#pragma unroll
    for (int ka = 0; ka < KWIN; ka++) {
        int aa = a + ka - 2;
        if (aa < 0 || aa > 15) continue;
#pragma unroll
        for (int kb = 0; kb < KWIN; kb++) {
            int bb = b_s + kb - 2;
            if (bb < 0 || bb > 15) continue;
            int nn = aa * 16 + bb;
            int koff = ka * KWIN + kb;
#pragma unroll
            for (int dk = 0; dk < 8; dk++) {
                float4 w4 = *(const float4*)&wst[koff * 32 + dk * 4];
                acc[dk * 4 + 0] += vt[(dk * 4 + 0) * TP + nn] * w4.x;
                acc[dk * 4 + 1] += vt[(dk * 4 + 1) * TP + nn] * w4.y;
                acc[dk * 4 + 2] += vt[(dk * 4 + 2) * TP + nn] * w4.z;
                acc[dk * 4 + 3] += vt[(dk * 4 + 3) * TP + nn] * w4.w;
            }
        }
    }
#pragma unroll
    for (int d = 0; d < 32; d++) acc[d] += bsm[d];

    // epilogue: fp16 hi/lo split, write ext row segment for proj GEMM
    const int b = bh / HEADS;
    const int h = bh - b * HEADS;
    __half hbuf[32], lbuf[32];
#pragma unroll
    for (int d = 0; d < 32; d++) {
        hbuf[d] = __float2half(acc[d]);
        lbuf[d] = __float2half(acc[d] - __half2float(hbuf[d]));
    }
    __half* dst = g_ae + ((size_t)(b * NTOK + i)) * KEXT + h * HD;
#pragma unroll
    for (int j = 0; j < 4; j++) {
        uint4 hp = ((const uint4*)hbuf)[j];
        uint4 lp = ((const uint4*)lbuf)[j];
        *(uint4*)&dst[j * 8]        = hp;   // seg 0: hi
        *(uint4*)&dst[DIMC + j * 8] = lp;   // seg 1: lo
    }
}

// ---------------- launch ----------------------------------------------------
extern "C" void kernel_launch(void* const* d_in, const int* in_sizes, int n_in,
                              void* d_out, int out_size)
{
    const float* x       = (const float*)d_in[0];
    const float* qkv_w   = (const float*)d_in[1];
    const float* qkv_b   = (const float*)d_in[2];
    const float* pos_enc = (const float*)d_in[3];
    const float* dwc_w   = (const float*)d_in[4];
    const float* dwc_b   = (const float*)d_in[5];
    const float* proj_w  = (const float*)d_in[6];
    const float* proj_b  = (const float*)d_in[7];
    float* out = (float*)d_out;

    cudaFuncSetAttribute(attn_kernel,
                         cudaFuncAttributeMaxDynamicSharedMemorySize, A2_BYTES);

    __half* ae; cudaGetSymbolAddress((void**)&ae, g_ae);
    __half* we; cudaGetSymbolAddress((void**)&we, g_we);
    __half* pe; cudaGetSymbolAddress((void**)&pe, g_pe);

    // 0) weight conversions -> fp16 [hi|hi]
    {
        int nw = 3 * DIMC * DIMC / 4;
        cvt_W_ext<<<(nw + 255) / 256, 256>>>(qkv_w, we, nw);
        int np = DIMC * DIMC / 4;
        cvt_W_ext<<<(np + 255) / 256, 256>>>(proj_w, pe, np);
    }

    // 1) qkv GEMM (fp16 TC, fused x conversion) -> g_q/g_k/g_v
    gemm_f16<0><<<dim3((3 * DIMC) / 128, MTOT / 128), 256>>>(
        nullptr, x, we, qkv_b, pos_enc, nullptr);

    // 2) fused linear attention + depthwise conv -> y_ext (g_ae)
    attn_kernel<<<BHTOT, 256, A2_BYTES>>>(dwc_w, dwc_b);

    // 3) proj GEMM (fp16 TC) -> out
    gemm_f16<1><<<dim3(DIMC / 128, MTOT / 128), 256>>>(
        ae, nullptr, pe, proj_b, nullptr, out);
}

// round 12
// speedup vs baseline: 1.2165x; 1.2165x over previous
#include <cuda_runtime.h>
#include <cuda_fp16.h>
#include <cstddef>
#include <cstdint>

#define DIMC   384
#define HEADS  12
#define HD     32
#define NTOK   256
#define BATCH  256
#define BHTOT  (BATCH * HEADS)      // 3072
#define MTOT   (BATCH * NTOK)       // 65536
#define KWIN   5
#define EPS    1e-6f
#define KEXT   (2 * DIMC)           // 768: A=[hi|lo], W=[hi|hi] (fp16 split)

// ---------------- scratch (device globals: allocation-free) ----------------
__device__ float g_q[(size_t)BHTOT * NTOK * HD];
__device__ float g_k[(size_t)BHTOT * NTOK * HD];
__device__ float g_v[(size_t)BHTOT * NTOK * HD];

__device__ __half g_ae[(size_t)MTOT * KEXT];       // y_ext (proj GEMM input)
__device__ __half g_we[(size_t)(3 * DIMC) * KEXT]; // qkv_w extended
__device__ __half g_pe[(size_t)DIMC * KEXT];       // proj_w extended

// ---------------- PTX helpers ----------------------------------------------
#define LDSM_X4(r0, r1, r2, r3, addr) \
    asm volatile("ldmatrix.sync.aligned.m8n8.x4.shared.b16 {%0,%1,%2,%3}, [%4];" \
        : "=r"(r0), "=r"(r1), "=r"(r2), "=r"(r3) : "r"(addr))

#define MMA_F16(c, a, b0, b1) \
    asm volatile("mma.sync.aligned.m16n8k16.row.col.f32.f16.f16.f32 " \
        "{%0,%1,%2,%3}, {%4,%5,%6,%7}, {%8,%9}, {%0,%1,%2,%3};" \
        : "+f"(c[0]), "+f"(c[1]), "+f"(c[2]), "+f"(c[3]) \
        : "r"(a[0]), "r"(a[1]), "r"(a[2]), "r"(a[3]), "r"(b0), "r"(b1))

// ---------------- fp32 -> fp16 [hi|hi] weight conversion --------------------
__global__ void __launch_bounds__(256) cvt_W_ext(
    const float* __restrict__ src, __half* __restrict__ dst, int nquads)
{
    int i = blockIdx.x * blockDim.x + threadIdx.x;
    if (i >= nquads) return;
    float4 v = *(const float4*)&src[(size_t)i * 4];
    int row = (i * 4) / DIMC;
    int k   = (i * 4) % DIMC;
    __half h[4];
    float vv[4] = {v.x, v.y, v.z, v.w};
#pragma unroll
    for (int j = 0; j < 4; j++) h[j] = __float2half(vv[j]);
    size_t base = (size_t)row * KEXT;
    uint2 hp;
    ((__half*)&hp)[0] = h[0]; ((__half*)&hp)[1] = h[1];
    ((__half*)&hp)[2] = h[2]; ((__half*)&hp)[3] = h[3];
    *(uint2*)&dst[base + k]        = hp;
    *(uint2*)&dst[base + DIMC + k] = hp;
}

// ---------------- fp16 tensor-core GEMM -------------------------------------
// C[m][n] = sum_k' Aext[m][k'] * Wext[n][k'], k' = 768. BM=BN=128, BK=32.
// 8 warps: warp grid 2(m) x 4(n), warp tile 64x32, mma m16n8k16.
// EPI=0: A loaded as fp32 x, converted hi/lo on the fly (k-tiles 0..11 = hi
// segment, 12..23 = lo segment); qkv epilogue (bias, relu, +pos, scatter).
// EPI=1: A from g_ae fp16 ext; proj epilogue (bias, fp32 store).
#define BKB 32
#define APITCH 40   // 32 + 8 pad (fp16) -> 80B row, conflict-free LDSM

template <int EPI>
__global__ void __launch_bounds__(256, 2) gemm_f16(
    const __half* __restrict__ Aext, const float* __restrict__ Araw,
    const __half* __restrict__ Wext,
    const float* __restrict__ bias, const float* __restrict__ pos_enc,
    float* __restrict__ Cout)
{
    __shared__ __half As[2][128][APITCH];
    __shared__ __half Bs[2][128][APITCH];

    const int tid  = threadIdx.x;
    const int lane = tid & 31;
    const int warp = tid >> 5;
    const int wm = warp >> 2;      // 0..1
    const int wn = warp & 3;       // 0..3
    const int bm = blockIdx.y * 128;
    const int bn = blockIdx.x * 128;

    int lrow[2], lch[2];
#pragma unroll
    for (int l = 0; l < 2; l++) {
        int idx = tid + l * 256;
        lrow[l] = idx >> 2;
        lch[l] = idx & 3;
    }

    // A-tile fragment loader: EPI=0 converts fp32 x -> fp16 hi/lo on the fly.
    auto loadA = [&](int kt, int l) -> int4 {
        if (EPI == 0) {
            int seg = kt / 12;
            int kc  = (kt - seg * 12) * 32 + lch[l] * 8;
            const float* src = Araw + (size_t)(bm + lrow[l]) * DIMC + kc;
            float4 xa = *(const float4*)src;
            float4 xb = *(const float4*)(src + 4);
            float v[8] = {xa.x, xa.y, xa.z, xa.w, xb.x, xb.y, xb.z, xb.w};
            union { int4 i4; __half h[8]; } u;
#pragma unroll
            for (int j = 0; j < 8; j++) {
                __half hi = __float2half(v[j]);
                u.h[j] = seg ? __float2half(v[j] - __half2float(hi)) : hi;
            }
            return u.i4;
        } else {
            return *(const int4*)&Aext[(size_t)(bm + lrow[l]) * KEXT +
                                       kt * BKB + lch[l] * 8];
        }
    };

    float acc[4][4][4];
#pragma unroll
    for (int mt = 0; mt < 4; mt++)
#pragma unroll
        for (int nt = 0; nt < 4; nt++)
#pragma unroll
            for (int e = 0; e < 4; e++) acc[mt][nt][e] = 0.f;

    int4 pa[2], pb[2];
#pragma unroll
    for (int l = 0; l < 2; l++) {
        pa[l] = loadA(0, l);
        pb[l] = *(const int4*)&Wext[(size_t)(bn + lrow[l]) * KEXT + lch[l] * 8];
    }
#pragma unroll
    for (int l = 0; l < 2; l++) {
        *(int4*)&As[0][lrow[l]][lch[l] * 8] = pa[l];
        *(int4*)&Bs[0][lrow[l]][lch[l] * 8] = pb[l];
    }
    __syncthreads();

    const int nkt = KEXT / BKB;   // 24
    for (int kt = 0; kt < nkt; kt++) {
        const int cur = kt & 1;
        const bool has_next = (kt + 1 < nkt);
        if (has_next) {
            int ko = (kt + 1) * BKB;
#pragma unroll
            for (int l = 0; l < 2; l++) {
                pa[l] = loadA(kt + 1, l);
                pb[l] = *(const int4*)&Wext[(size_t)(bn + lrow[l]) * KEXT + ko + lch[l] * 8];
            }
        }

#pragma unroll
        for (int s = 0; s < 2; s++) {       // two k16 steps
            uint32_t a[4][4];
#pragma unroll
            for (int mt = 0; mt < 4; mt++) {
                int r = wm * 64 + mt * 16 + (lane & 15);
                int c = s * 16 + ((lane >> 4) << 3);
                uint32_t ad = (uint32_t)__cvta_generic_to_shared(&As[cur][r][c]);
                LDSM_X4(a[mt][0], a[mt][1], a[mt][2], a[mt][3], ad);
            }
            uint32_t b[4][2];
#pragma unroll
            for (int nt2 = 0; nt2 < 2; nt2++) {
                int r = wn * 32 + nt2 * 16 + ((lane >> 4) << 3) + (lane & 7);
                int c = s * 16 + (((lane >> 3) & 1) << 3);
                uint32_t ad = (uint32_t)__cvta_generic_to_shared(&Bs[cur][r][c]);
                LDSM_X4(b[nt2 * 2][0], b[nt2 * 2][1],
                        b[nt2 * 2 + 1][0], b[nt2 * 2 + 1][1], ad);
            }
#pragma unroll
            for (int mt = 0; mt < 4; mt++)
#pragma unroll
                for (int nt = 0; nt < 4; nt++)
                    MMA_F16(acc[mt][nt], a[mt], b[nt][0], b[nt][1]);
        }

        if (has_next) {
            const int nxt = cur ^ 1;
#pragma unroll
            for (int l = 0; l < 2; l++) {
                *(int4*)&As[nxt][lrow[l]][lch[l] * 8] = pa[l];
                *(int4*)&Bs[nxt][lrow[l]][lch[l] * 8] = pb[l];
            }
        }
        __syncthreads();
    }

    // ---- epilogue ----
    if (EPI == 0) {
#pragma unroll
        for (int mt = 0; mt < 4; mt++) {
            int m0 = bm + wm * 64 + mt * 16 + (lane >> 2);
#pragma unroll
            for (int nt = 0; nt < 4; nt++) {
                int n0 = bn + wn * 32 + nt * 8 + (lane & 3) * 2;
#pragma unroll
                for (int e = 0; e < 4; e++) {
                    int m = m0 + (e >> 1) * 8;
                    int n = n0 + (e & 1);
                    int b = m >> 8;
                    int i = m & 255;
                    float val = acc[mt][nt][e] + bias[n];
                    int region = n / DIMC;
                    int ch = n - region * DIMC;
                    int h = ch >> 5;
                    int d = ch & 31;
                    size_t dst = ((size_t)(b * HEADS + h) * NTOK + i) * HD + d;
                    if (region == 0) {
                        g_q[dst] = fmaxf(val, 0.f);
                    } else if (region == 1) {
                        g_k[dst] = fmaxf(val + pos_enc[(size_t)i * DIMC + ch], 0.f);
                    } else {
                        g_v[dst] = val;
                    }
                }
            }
        }
    } else {
#pragma unroll
        for (int mt = 0; mt < 4; mt++) {
            int m0 = bm + wm * 64 + mt * 16 + (lane >> 2);
#pragma unroll
            for (int nt = 0; nt < 4; nt++) {
                int n0 = bn + wn * 32 + nt * 8 + (lane & 3) * 2;
                float2 lo, hi2;
                lo.x  = acc[mt][nt][0] + bias[n0];
                lo.y  = acc[mt][nt][1] + bias[n0 + 1];
                hi2.x = acc[mt][nt][2] + bias[n0];
                hi2.y = acc[mt][nt][3] + bias[n0 + 1];
                *(float2*)&Cout[(size_t)m0 * DIMC + n0] = lo;
                *(float2*)&Cout[(size_t)(m0 + 8) * DIMC + n0] = hi2;
            }
        }
    }
}

// ---------------- fused linear attention + depthwise conv (R10 layout) -----
// one block per (b,h). smem: q/k/v tiles [256][33] + kv [32][33] + ksum + w/b
#define SM_Q   0
#define SM_K   (256 * 33)
#define SM_V   (2 * 256 * 33)
#define SM_KV  (3 * 256 * 33)          // 25344
#define SM_KS  (SM_KV + 32 * 33)       // 26400
#define SM_W   (SM_KS + 32)            // 26432
#define SM_B   (SM_W + 800)            // 27232
#define SM_FLOATS (SM_B + 32)          // 27264
#define SMEM_BYTES (SM_FLOATS * 4)     // 109056

__global__ void __launch_bounds__(256) attn_kernel(
    const float* __restrict__ dwc_w, const float* __restrict__ dwc_b)
{
    extern __shared__ float sm[];
    float* qs   = sm + SM_Q;
    float* ks   = sm + SM_K;
    float* vs   = sm + SM_V;
    float* kvs  = sm + SM_KV;
    float* ksum = sm + SM_KS;
    float* ws   = sm + SM_W;
    float* bsm  = sm + SM_B;

    const int tid = threadIdx.x;
    const int bh = blockIdx.x;
    const size_t base = (size_t)bh * (NTOK * HD);

    for (int idx = tid; idx < 2048; idx += 256) {
        int row = idx >> 3;
        int col = (idx & 7) * 4;
        float4 t;
        t = *(const float4*)&g_q[base + row * 32 + col];
        qs[row * 33 + col] = t.x; qs[row * 33 + col + 1] = t.y;
        qs[row * 33 + col + 2] = t.z; qs[row * 33 + col + 3] = t.w;
        t = *(const float4*)&g_k[base + row * 32 + col];
        ks[row * 33 + col] = t.x; ks[row * 33 + col + 1] = t.y;
        ks[row * 33 + col + 2] = t.z; ks[row * 33 + col + 3] = t.w;
        t = *(const float4*)&g_v[base + row * 32 + col];
        vs[row * 33 + col] = t.x; vs[row * 33 + col + 1] = t.y;
        vs[row * 33 + col + 2] = t.z; vs[row * 33 + col + 3] = t.w;
    }
    for (int idx = tid; idx < 800; idx += 256) ws[idx] = dwc_w[idx];
    if (tid < 32) bsm[tid] = dwc_b[tid];
    __syncthreads();

    {
        const int c = tid >> 3;
        const int d0 = tid & 7;
        float a0 = 0.f, a1 = 0.f, a2 = 0.f, a3 = 0.f, s = 0.f;
#pragma unroll 4
        for (int j = 0; j < 256; j++) {
            float kk = ks[j * 33 + c];
            a0 += kk * vs[j * 33 + d0];
            a1 += kk * vs[j * 33 + d0 + 8];
            a2 += kk * vs[j * 33 + d0 + 16];
            a3 += kk * vs[j * 33 + d0 + 24];
            s += kk;
        }
        kvs[c * 33 + d0]      = a0;
        kvs[c * 33 + d0 + 8]  = a1;
        kvs[c * 33 + d0 + 16] = a2;
        kvs[c * 33 + d0 + 24] = a3;
        if (d0 == 0) ksum[c] = s;
    }
    __syncthreads();

    const int i = tid;
    float qr[32];
#pragma unroll
    for (int c = 0; c < 32; c++) qr[c] = qs[i * 33 + c];

    float zden = EPS;
#pragma unroll
    for (int c = 0; c < 32; c++) zden += qr[c] * ksum[c];
    const float z = 1.0f / zden;

    float acc[32];
#pragma unroll
    for (int d = 0; d < 32; d++) acc[d] = 0.f;
#pragma unroll
    for (int c = 0; c < 32; c++) {
        float qc = qr[c];
#pragma unroll
        for (int d = 0; d < 32; d++) acc[d] += qc * kvs[c * 33 + d];
    }
#pragma unroll
    for (int d = 0; d < 32; d++) acc[d] *= z;

    const int a = i >> 4;
    const int b_s = i & 15;
#pragma unroll
    for (int ka = 0; ka < KWIN; ka++) {
        int aa = a + ka - 2;
        if (aa < 0 || aa > 15) continue;
#pragma unroll
        for (int kb = 0; kb < KWIN; kb++) {
            int bb = b_s + kb - 2;
            if (bb < 0 || bb > 15) continue;
            int nn = aa * 16 + bb;
#pragma unroll
            for (int d = 0; d < 32; d++)
                acc[d] += vs[nn * 33 + d] * ws[d * 25 + ka * KWIN + kb];
        }
    }
#pragma unroll
    for (int d = 0; d < 32; d++) acc[d] += bsm[d];

    // epilogue: fp16 hi/lo split, write extended row segment for proj GEMM
    const int b = bh / HEADS;
    const int h = bh - b * HEADS;
    __half hbuf[32], lbuf[32];
#pragma unroll
    for (int d = 0; d < 32; d++) {
        hbuf[d] = __float2half(acc[d]);
        lbuf[d] = __float2half(acc[d] - __half2float(hbuf[d]));
    }
    __half* dst = g_ae + ((size_t)(b * NTOK + i)) * KEXT + h * HD;
#pragma unroll
    for (int j = 0; j < 4; j++) {
        uint4 hp = ((const uint4*)hbuf)[j];
        uint4 lp = ((const uint4*)lbuf)[j];
        *(uint4*)&dst[j * 8]        = hp;   // seg 0: hi
        *(uint4*)&dst[DIMC + j * 8] = lp;   // seg 1: lo
    }
}

// ---------------- launch ----------------------------------------------------
extern "C" void kernel_launch(void* const* d_in, const int* in_sizes, int n_in,
                              void* d_out, int out_size)
{
    const float* x       = (const float*)d_in[0];
    const float* qkv_w   = (const float*)d_in[1];
    const float* qkv_b   = (const float*)d_in[2];
    const float* pos_enc = (const float*)d_in[3];
    const float* dwc_w   = (const float*)d_in[4];
    const float* dwc_b   = (const float*)d_in[5];
    const float* proj_w  = (const float*)d_in[6];
    const float* proj_b  = (const float*)d_in[7];
    float* out = (float*)d_out;

    cudaFuncSetAttribute(attn_kernel,
                         cudaFuncAttributeMaxDynamicSharedMemorySize, SMEM_BYTES);

    __half* ae; cudaGetSymbolAddress((void**)&ae, g_ae);
    __half* we; cudaGetSymbolAddress((void**)&we, g_we);
    __half* pe; cudaGetSymbolAddress((void**)&pe, g_pe);

    // 0) weight conversions -> fp16 [hi|hi]
    {
        int nw = 3 * DIMC * DIMC / 4;
        cvt_W_ext<<<(nw + 255) / 256, 256>>>(qkv_w, we, nw);
        int np = DIMC * DIMC / 4;
        cvt_W_ext<<<(np + 255) / 256, 256>>>(proj_w, pe, np);
    }

    // 1) qkv GEMM (fp16 TC, fused x conversion) -> g_q/g_k/g_v
    gemm_f16<0><<<dim3((3 * DIMC) / 128, MTOT / 128), 256>>>(
        nullptr, x, we, qkv_b, pos_enc, nullptr);

    // 2) fused linear attention + depthwise conv -> y_ext (g_ae)
    attn_kernel<<<BHTOT, 256, SMEM_BYTES>>>(dwc_w, dwc_b);

    // 3) proj GEMM (fp16 TC) -> out
    gemm_f16<1><<<dim3(DIMC / 128, MTOT / 128), 256>>>(
        ae, nullptr, pe, proj_b, nullptr, out);
}

// round 14
// speedup vs baseline: 1.3569x; 1.1154x over previous
#include <cuda_runtime.h>
#include <cuda_fp16.h>
#include <cstddef>
#include <cstdint>

#define DIMC   384
#define HEADS  12
#define HD     32
#define NTOK   256
#define BATCH  256
#define BHTOT  (BATCH * HEADS)      // 3072
#define MTOT   (BATCH * NTOK)       // 65536
#define KWIN   5
#define EPS    1e-6f
#define KEXT   (2 * DIMC)           // 768: A=[hi|lo], W=[hi|hi] (fp16 split)

// ---------------- scratch (device globals: allocation-free) ----------------
__device__ float g_q[(size_t)BHTOT * NTOK * HD];
__device__ float g_k[(size_t)BHTOT * NTOK * HD];
__device__ float g_v[(size_t)BHTOT * NTOK * HD];

__device__ __half g_ae[(size_t)MTOT * KEXT];       // x_ext then y_ext
__device__ __half g_we[(size_t)(3 * DIMC) * KEXT]; // qkv_w extended
__device__ __half g_pe[(size_t)DIMC * KEXT];       // proj_w extended

// ---------------- PTX helpers ----------------------------------------------
#define LDSM_X4(r0, r1, r2, r3, addr) \
    asm volatile("ldmatrix.sync.aligned.m8n8.x4.shared.b16 {%0,%1,%2,%3}, [%4];" \
        : "=r"(r0), "=r"(r1), "=r"(r2), "=r"(r3) : "r"(addr))

#define MMA_F16(c, a, b0, b1) \
    asm volatile("mma.sync.aligned.m16n8k16.row.col.f32.f16.f16.f32 " \
        "{%0,%1,%2,%3}, {%4,%5,%6,%7}, {%8,%9}, {%0,%1,%2,%3};" \
        : "+f"(c[0]), "+f"(c[1]), "+f"(c[2]), "+f"(c[3]) \
        : "r"(a[0]), "r"(a[1]), "r"(a[2]), "r"(a[3]), "r"(b0), "r"(b1))

// ---------------- fp32 -> fp16 hi/lo extended conversions -------------------
// A-style: [hi | lo]
__global__ void __launch_bounds__(256) cvt_A_ext(
    const float* __restrict__ src, __half* __restrict__ dst, int nquads)
{
    int i = blockIdx.x * blockDim.x + threadIdx.x;
    if (i >= nquads) return;
    float4 v = *(const float4*)&src[(size_t)i * 4];
    int row = (i * 4) / DIMC;
    int k   = (i * 4) % DIMC;
    __half h[4], l[4];
    float vv[4] = {v.x, v.y, v.z, v.w};
#pragma unroll
    for (int j = 0; j < 4; j++) {
        h[j] = __float2half(vv[j]);
        l[j] = __float2half(vv[j] - __half2float(h[j]));
    }
    size_t base = (size_t)row * KEXT;
    uint2 hp, lp;
    ((__half*)&hp)[0] = h[0]; ((__half*)&hp)[1] = h[1];
    ((__half*)&hp)[2] = h[2]; ((__half*)&hp)[3] = h[3];
    ((__half*)&lp)[0] = l[0]; ((__half*)&lp)[1] = l[1];
    ((__half*)&lp)[2] = l[2]; ((__half*)&lp)[3] = l[3];
    *(uint2*)&dst[base + k]        = hp;
    *(uint2*)&dst[base + DIMC + k] = lp;
}

// W-style: [hi | hi]
__global__ void __launch_bounds__(256) cvt_W_ext(
    const float* __restrict__ src, __half* __restrict__ dst, int nquads)
{
    int i = blockIdx.x * blockDim.x + threadIdx.x;
    if (i >= nquads) return;
    float4 v = *(const float4*)&src[(size_t)i * 4];
    int row = (i * 4) / DIMC;
    int k   = (i * 4) % DIMC;
    __half h[4];
    float vv[4] = {v.x, v.y, v.z, v.w};
#pragma unroll
    for (int j = 0; j < 4; j++) h[j] = __float2half(vv[j]);
    size_t base = (size_t)row * KEXT;
    uint2 hp;
    ((__half*)&hp)[0] = h[0]; ((__half*)&hp)[1] = h[1];
    ((__half*)&hp)[2] = h[2]; ((__half*)&hp)[3] = h[3];
    *(uint2*)&dst[base + k]        = hp;
    *(uint2*)&dst[base + DIMC + k] = hp;
}

// ---------------- fp16 tensor-core GEMM (R10 proven) ------------------------
#define BKB 32
#define APITCH 40   // 32 + 8 pad (fp16) -> 80B row, conflict-free LDSM

template <int EPI>
__global__ void __launch_bounds__(256, 2) gemm_f16(
    const __half* __restrict__ Aext, const __half* __restrict__ Wext,
    const float* __restrict__ bias, const float* __restrict__ pos_enc,
    float* __restrict__ Cout)
{
    __shared__ __half As[2][128][APITCH];
    __shared__ __half Bs[2][128][APITCH];

    const int tid  = threadIdx.x;
    const int lane = tid & 31;
    const int warp = tid >> 5;
    const int wm = warp >> 2;      // 0..1
    const int wn = warp & 3;       // 0..3
    const int bm = blockIdx.y * 128;
    const int bn = blockIdx.x * 128;

    int lrow[2], lch[2];
#pragma unroll
    for (int l = 0; l < 2; l++) {
        int idx = tid + l * 256;
        lrow[l] = idx >> 2;
        lch[l] = idx & 3;
    }

    float acc[4][4][4];
#pragma unroll
    for (int mt = 0; mt < 4; mt++)
#pragma unroll
        for (int nt = 0; nt < 4; nt++)
#pragma unroll
            for (int e = 0; e < 4; e++) acc[mt][nt][e] = 0.f;

    int4 pa[2], pb[2];
#pragma unroll
    for (int l = 0; l < 2; l++) {
        pa[l] = *(const int4*)&Aext[(size_t)(bm + lrow[l]) * KEXT + lch[l] * 8];
        pb[l] = *(const int4*)&Wext[(size_t)(bn + lrow[l]) * KEXT + lch[l] * 8];
    }
#pragma unroll
    for (int l = 0; l < 2; l++) {
        *(int4*)&As[0][lrow[l]][lch[l] * 8] = pa[l];
        *(int4*)&Bs[0][lrow[l]][lch[l] * 8] = pb[l];
    }
    __syncthreads();

    const int nkt = KEXT / BKB;   // 24
    for (int kt = 0; kt < nkt; kt++) {
        const int cur = kt & 1;
        const bool has_next = (kt + 1 < nkt);
        if (has_next) {
            int ko = (kt + 1) * BKB;
#pragma unroll
            for (int l = 0; l < 2; l++) {
                pa[l] = *(const int4*)&Aext[(size_t)(bm + lrow[l]) * KEXT + ko + lch[l] * 8];
                pb[l] = *(const int4*)&Wext[(size_t)(bn + lrow[l]) * KEXT + ko + lch[l] * 8];
            }
        }

#pragma unroll
        for (int s = 0; s < 2; s++) {
            uint32_t a[4][4];
#pragma unroll
            for (int mt = 0; mt < 4; mt++) {
                int r = wm * 64 + mt * 16 + (lane & 15);
                int c = s * 16 + ((lane >> 4) << 3);
                uint32_t ad = (uint32_t)__cvta_generic_to_shared(&As[cur][r][c]);
                LDSM_X4(a[mt][0], a[mt][1], a[mt][2], a[mt][3], ad);
            }
            uint32_t b[4][2];
#pragma unroll
            for (int nt2 = 0; nt2 < 2; nt2++) {
                int r = wn * 32 + nt2 * 16 + ((lane >> 4) << 3) + (lane & 7);
                int c = s * 16 + (((lane >> 3) & 1) << 3);
                uint32_t ad = (uint32_t)__cvta_generic_to_shared(&Bs[cur][r][c]);
                LDSM_X4(b[nt2 * 2][0], b[nt2 * 2][1],
                        b[nt2 * 2 + 1][0], b[nt2 * 2 + 1][1], ad);
            }
#pragma unroll
            for (int mt = 0; mt < 4; mt++)
#pragma unroll
                for (int nt = 0; nt < 4; nt++)
                    MMA_F16(acc[mt][nt], a[mt], b[nt][0], b[nt][1]);
        }

        if (has_next) {
            const int nxt = cur ^ 1;
#pragma unroll
            for (int l = 0; l < 2; l++) {
                *(int4*)&As[nxt][lrow[l]][lch[l] * 8] = pa[l];
                *(int4*)&Bs[nxt][lrow[l]][lch[l] * 8] = pb[l];
            }
        }
        __syncthreads();
    }

    if (EPI == 0) {
#pragma unroll
        for (int mt = 0; mt < 4; mt++) {
            int m0 = bm + wm * 64 + mt * 16 + (lane >> 2);
#pragma unroll
            for (int nt = 0; nt < 4; nt++) {
                int n0 = bn + wn * 32 + nt * 8 + (lane & 3) * 2;
#pragma unroll
                for (int e = 0; e < 4; e++) {
                    int m = m0 + (e >> 1) * 8;
                    int n = n0 + (e & 1);
                    int b = m >> 8;
                    int i = m & 255;
                    float val = acc[mt][nt][e] + bias[n];
                    int region = n / DIMC;
                    int ch = n - region * DIMC;
                    int h = ch >> 5;
                    int d = ch & 31;
                    size_t dst = ((size_t)(b * HEADS + h) * NTOK + i) * HD + d;
                    if (region == 0) {
                        g_q[dst] = fmaxf(val, 0.f);
                    } else if (region == 1) {
                        g_k[dst] = fmaxf(val + pos_enc[(size_t)i * DIMC + ch], 0.f);
                    } else {
                        g_v[dst] = val;
                    }
                }
            }
        }
    } else {
#pragma unroll
        for (int mt = 0; mt < 4; mt++) {
            int m0 = bm + wm * 64 + mt * 16 + (lane >> 2);
#pragma unroll
            for (int nt = 0; nt < 4; nt++) {
                int n0 = bn + wn * 32 + nt * 8 + (lane & 3) * 2;
                float2 lo, hi2;
                lo.x  = acc[mt][nt][0] + bias[n0];
                lo.y  = acc[mt][nt][1] + bias[n0 + 1];
                hi2.x = acc[mt][nt][2] + bias[n0];
                hi2.y = acc[mt][nt][3] + bias[n0 + 1];
                *(float2*)&Cout[(size_t)m0 * DIMC + n0] = lo;
                *(float2*)&Cout[(size_t)(m0 + 8) * DIMC + n0] = hi2;
            }
        }
    }
}

// ---------------- fused linear attention + depthwise conv (v3) -------------
// Phase 1 j-split: warp w owns j in [32w, 32w+32), full 32x32 partial kv in
// registers (lane = c). v at pitch 32 (aligned float4 BROADCAST reads -> no
// conflicts); k at pitch 32 (lane-consecutive). Partials reduced via a
// pitch-33 smem overlay on the then-dead k/v-p32 region. Conv uses the
// pitch-33 v copy (conflict-free scalar) + [tap][d]-transposed weights
// (float4 broadcast). q read directly from gmem.
// smem (floats):
#define AT_KS    0                      // k p32: 256*32 = 8192
#define AT_VS32  8192                   // v p32: 8192
#define AT_VS33  16384                  // v p33: 256*33 = 8448
#define AT_KVF   24832                  // kv: 32*36 = 1152
#define AT_KSUM  25984                  // 32
#define AT_WS    26016                  // wst[tap][d]: 800
#define AT_BS    26816                  // 32
#define AT_FLOATS 26848
#define AT_BYTES (AT_FLOATS * 4)        // 107392 bytes -> 2 CTAs/SM

__global__ void __launch_bounds__(256, 2) attn_kernel(
    const float* __restrict__ dwc_w, const float* __restrict__ dwc_b)
{
    extern __shared__ float sm[];
    float* ks32 = sm + AT_KS;
    float* vs32 = sm + AT_VS32;
    float* vs33 = sm + AT_VS33;
    float* kvf  = sm + AT_KVF;
    float* ksum = sm + AT_KSUM;
    float* wst  = sm + AT_WS;
    float* bsm  = sm + AT_BS;
    float* part = sm;                   // overlay: [8][32][33], used post-phase1

    const int tid = threadIdx.x;
    const int bh = blockIdx.x;
    const size_t base = (size_t)bh * (NTOK * HD);

    // load k (p32), v (p32 + p33)
    for (int idx = tid; idx < 2048; idx += 256) {
        int row = idx >> 3;
        int col = (idx & 7) * 4;
        float4 t = *(const float4*)&g_k[base + row * 32 + col];
        *(float4*)&ks32[row * 32 + col] = t;
        t = *(const float4*)&g_v[base + row * 32 + col];
        *(float4*)&vs32[row * 32 + col] = t;
        vs33[row * 33 + col + 0] = t.x;
        vs33[row * 33 + col + 1] = t.y;
        vs33[row * 33 + col + 2] = t.z;
        vs33[row * 33 + col + 3] = t.w;
    }
    // conv weights transposed: wst[tap][d] = dwc_w[d*25 + tap]
    for (int idx = tid; idx < 800; idx += 256)
        wst[idx] = dwc_w[(idx & 31) * 25 + (idx >> 5)];
    if (tid < 32) bsm[tid] = dwc_b[tid];
    __syncthreads();

    // phase 1: per-warp partial kv over j-slice; lane = c owns all 32 d
    {
        const int w = tid >> 5;
        const int lane = tid & 31;
        float pacc[32];
#pragma unroll
        for (int d = 0; d < 32; d++) pacc[d] = 0.f;
        float psum = 0.f;
        const int j0 = w * 32;
#pragma unroll 4
        for (int jj = 0; jj < 32; jj++) {
            int j = j0 + jj;
            float kc = ks32[j * 32 + lane];
            psum += kc;
#pragma unroll
            for (int dq = 0; dq < 8; dq++) {
                float4 v4 = *(const float4*)&vs32[j * 32 + dq * 4];  // broadcast
                pacc[dq * 4 + 0] += kc * v4.x;
                pacc[dq * 4 + 1] += kc * v4.y;
                pacc[dq * 4 + 2] += kc * v4.z;
                pacc[dq * 4 + 3] += kc * v4.w;
            }
        }
        __syncthreads();   // all warps done reading ks32/vs32 -> overlay safe
        float* pw = part + w * 1056 + lane * 33;
#pragma unroll
        for (int d = 0; d < 32; d++) pw[d] = pacc[d];
        pw[32] = psum;
    }
    __syncthreads();

    // reduce partials -> kvf (pitch 36, aligned float4) + ksum
    {
        const int c  = tid >> 3;
        const int d0 = (tid & 7) * 4;
        float r0 = 0.f, r1 = 0.f, r2 = 0.f, r3 = 0.f;
#pragma unroll
        for (int w = 0; w < 8; w++) {
            const float* p = part + w * 1056 + c * 33 + d0;
            r0 += p[0]; r1 += p[1]; r2 += p[2]; r3 += p[3];
        }
        float4 o; o.x = r0; o.y = r1; o.z = r2; o.w = r3;
        *(float4*)&kvf[c * 36 + d0] = o;
        if ((tid & 7) == 0) {
            float s = 0.f;
#pragma unroll
            for (int w = 0; w < 8; w++) s += part[w * 1056 + c * 33 + 32];
            ksum[c] = s;
        }
    }
    __syncthreads();

    // phase 2: per-token output
    const int i = tid;
    float qr[32];
#pragma unroll
    for (int j2 = 0; j2 < 8; j2++)
        *(float4*)&qr[j2 * 4] = *(const float4*)&g_q[base + (size_t)i * 32 + j2 * 4];

    float zden = EPS;
#pragma unroll
    for (int c = 0; c < 32; c++) zden += qr[c] * ksum[c];
    const float z = 1.0f / zden;

    float acc[32];
#pragma unroll
    for (int d = 0; d < 32; d++) acc[d] = 0.f;
#pragma unroll
    for (int c = 0; c < 32; c++) {
        float qc = qr[c];
#pragma unroll
        for (int dq = 0; dq < 8; dq++) {
            float4 kv4 = *(const float4*)&kvf[c * 36 + dq * 4];  // broadcast
            acc[dq * 4 + 0] += qc * kv4.x;
            acc[dq * 4 + 1] += qc * kv4.y;
            acc[dq * 4 + 2] += qc * kv4.z;
            acc[dq * 4 + 3] += qc * kv4.w;
        }
    }
#pragma unroll
    for (int d = 0; d < 32; d++) acc[d] *= z;

    // depthwise 5x5 conv: v from pitch-33 copy (conflict-free), w broadcast
    const int a = i >> 4;
    const int b_s = i & 15;
#pragma unroll
    for (int ka = 0; ka < KWIN; ka++) {
        int aa = a + ka - 2;
        if (aa < 0 || aa > 15) continue;
#pragma unroll
        for (int kb = 0; kb < KWIN; kb++) {
            int bb = b_s + kb - 2;
            if (bb < 0 || bb > 15) continue;
            int nn = aa * 16 + bb;
            int koff = ka * KWIN + kb;
#pragma unroll
            for (int dq = 0; dq < 8; dq++) {
                float4 w4 = *(const float4*)&wst[koff * 32 + dq * 4];  // broadcast
                acc[dq * 4 + 0] += vs33[nn * 33 + dq * 4 + 0] * w4.x;
                acc[dq * 4 + 1] += vs33[nn * 33 + dq * 4 + 1] * w4.y;
                acc[dq * 4 + 2] += vs33[nn * 33 + dq * 4 + 2] * w4.z;
                acc[dq * 4 + 3] += vs33[nn * 33 + dq * 4 + 3] * w4.w;
            }
        }
    }
#pragma unroll
    for (int d = 0; d < 32; d++) acc[d] += bsm[d];

    // epilogue: fp16 hi/lo split -> g_ae extended row for proj GEMM
    const int b = bh / HEADS;
    const int h = bh - b * HEADS;
    __half hbuf[32], lbuf[32];
#pragma unroll
    for (int d = 0; d < 32; d++) {
        hbuf[d] = __float2half(acc[d]);
        lbuf[d] = __float2half(acc[d] - __half2float(hbuf[d]));
    }
    __half* dst = g_ae + ((size_t)(b * NTOK + i)) * KEXT + h * HD;
#pragma unroll
    for (int j = 0; j < 4; j++) {
        uint4 hp = ((const uint4*)hbuf)[j];
        uint4 lp = ((const uint4*)lbuf)[j];
        *(uint4*)&dst[j * 8]        = hp;   // seg 0: hi
        *(uint4*)&dst[DIMC + j * 8] = lp;   // seg 1: lo
    }
}

// ---------------- launch ----------------------------------------------------
extern "C" void kernel_launch(void* const* d_in, const int* in_sizes, int n_in,
                              void* d_out, int out_size)
{
    const float* x       = (const float*)d_in[0];
    const float* qkv_w   = (const float*)d_in[1];
    const float* qkv_b   = (const float*)d_in[2];
    const float* pos_enc = (const float*)d_in[3];
    const float* dwc_w   = (const float*)d_in[4];
    const float* dwc_b   = (const float*)d_in[5];
    const float* proj_w  = (const float*)d_in[6];
    const float* proj_b  = (const float*)d_in[7];
    float* out = (float*)d_out;

    cudaFuncSetAttribute(attn_kernel,
                         cudaFuncAttributeMaxDynamicSharedMemorySize, AT_BYTES);

    __half* ae; cudaGetSymbolAddress((void**)&ae, g_ae);
    __half* we; cudaGetSymbolAddress((void**)&we, g_we);
    __half* pe; cudaGetSymbolAddress((void**)&pe, g_pe);

    // 0) conversions: x -> [hi|lo], qkv_w/proj_w -> [hi|hi]
    {
        int nq = MTOT * DIMC / 4;
        cvt_A_ext<<<(nq + 255) / 256, 256>>>(x, ae, nq);
        int nw = 3 * DIMC * DIMC / 4;
        cvt_W_ext<<<(nw + 255) / 256, 256>>>(qkv_w, we, nw);
        int np = DIMC * DIMC / 4;
        cvt_W_ext<<<(np + 255) / 256, 256>>>(proj_w, pe, np);
    }

    // 1) qkv GEMM (fp16 TC) + fused epilogue -> g_q/g_k/g_v
    gemm_f16<0><<<dim3((3 * DIMC) / 128, MTOT / 128), 256>>>(
        ae, we, qkv_b, pos_enc, nullptr);

    // 2) fused linear attention + depthwise conv -> y_ext (reuses g_ae)
    attn_kernel<<<BHTOT, 256, AT_BYTES>>>(dwc_w, dwc_b);

    // 3) proj GEMM (fp16 TC) -> out
    gemm_f16<1><<<dim3(DIMC / 128, MTOT / 128), 256>>>(
        ae, pe, proj_b, nullptr, out);
}

// round 15
// speedup vs baseline: 1.6503x; 1.2163x over previous
#include <cuda_runtime.h>
#include <cuda_fp16.h>
#include <cstddef>
#include <cstdint>

#define DIMC   384
#define HEADS  12
#define HD     32
#define NTOK   256
#define BATCH  256
#define BHTOT  (BATCH * HEADS)      // 3072
#define MTOT   (BATCH * NTOK)       // 65536
#define KWIN   5
#define EPS    1e-6f
#define KEXT   (2 * DIMC)           // 768: A=[hi|lo], W=[hi|hi] (fp16 split)

// ---------------- scratch (device globals: allocation-free) ----------------
__device__ float g_q[(size_t)BHTOT * NTOK * HD];
__device__ float g_k[(size_t)BHTOT * NTOK * HD];
__device__ float g_v[(size_t)BHTOT * NTOK * HD];

__device__ __half g_ae[(size_t)MTOT * KEXT];       // x_ext then y_ext
__device__ __half g_we[(size_t)(3 * DIMC) * KEXT]; // qkv_w extended
__device__ __half g_pe[(size_t)DIMC * KEXT];       // proj_w extended

// ---------------- PTX helpers ----------------------------------------------
#define LDSM_X4(r0, r1, r2, r3, addr) \
    asm volatile("ldmatrix.sync.aligned.m8n8.x4.shared.b16 {%0,%1,%2,%3}, [%4];" \
        : "=r"(r0), "=r"(r1), "=r"(r2), "=r"(r3) : "r"(addr))

#define MMA_F16(c, a, b0, b1) \
    asm volatile("mma.sync.aligned.m16n8k16.row.col.f32.f16.f16.f32 " \
        "{%0,%1,%2,%3}, {%4,%5,%6,%7}, {%8,%9}, {%0,%1,%2,%3};" \
        : "+f"(c[0]), "+f"(c[1]), "+f"(c[2]), "+f"(c[3]) \
        : "r"(a[0]), "r"(a[1]), "r"(a[2]), "r"(a[3]), "r"(b0), "r"(b1))

#define CP_ASYNC_16(smem_u32, gptr) \
    asm volatile("cp.async.cg.shared.global [%0], [%1], 16;" \
        :: "r"(smem_u32), "l"(gptr))
#define CP_ASYNC_COMMIT() asm volatile("cp.async.commit_group;" ::: "memory")
#define CP_ASYNC_WAIT(N)  asm volatile("cp.async.wait_group %0;" :: "n"(N) : "memory")

// ---------------- fp32 -> fp16 hi/lo extended conversions -------------------
// A-style: [hi | lo]
__global__ void __launch_bounds__(256) cvt_A_ext(
    const float* __restrict__ src, __half* __restrict__ dst, int nquads)
{
    int i = blockIdx.x * blockDim.x + threadIdx.x;
    if (i >= nquads) return;
    float4 v = *(const float4*)&src[(size_t)i * 4];
    int row = (i * 4) / DIMC;
    int k   = (i * 4) % DIMC;
    __half h[4], l[4];
    float vv[4] = {v.x, v.y, v.z, v.w};
#pragma unroll
    for (int j = 0; j < 4; j++) {
        h[j] = __float2half(vv[j]);
        l[j] = __float2half(vv[j] - __half2float(h[j]));
    }
    size_t base = (size_t)row * KEXT;
    uint2 hp, lp;
    ((__half*)&hp)[0] = h[0]; ((__half*)&hp)[1] = h[1];
    ((__half*)&hp)[2] = h[2]; ((__half*)&hp)[3] = h[3];
    ((__half*)&lp)[0] = l[0]; ((__half*)&lp)[1] = l[1];
    ((__half*)&lp)[2] = l[2]; ((__half*)&lp)[3] = l[3];
    *(uint2*)&dst[base + k]        = hp;
    *(uint2*)&dst[base + DIMC + k] = lp;
}

// W-style: [hi | hi]
__global__ void __launch_bounds__(256) cvt_W_ext(
    const float* __restrict__ src, __half* __restrict__ dst, int nquads)
{
    int i = blockIdx.x * blockDim.x + threadIdx.x;
    if (i >= nquads) return;
    float4 v = *(const float4*)&src[(size_t)i * 4];
    int row = (i * 4) / DIMC;
    int k   = (i * 4) % DIMC;
    __half h[4];
    float vv[4] = {v.x, v.y, v.z, v.w};
#pragma unroll
    for (int j = 0; j < 4; j++) h[j] = __float2half(vv[j]);
    size_t base = (size_t)row * KEXT;
    uint2 hp;
    ((__half*)&hp)[0] = h[0]; ((__half*)&hp)[1] = h[1];
    ((__half*)&hp)[2] = h[2]; ((__half*)&hp)[3] = h[3];
    *(uint2*)&dst[base + k]        = hp;
    *(uint2*)&dst[base + DIMC + k] = hp;
}

// ---------------- fp16 tensor-core GEMM (BK=64, XOR-swizzled, cp.async) -----
// C[m][n] = sum_k' Aext[m][k'] * Wext[n][k'], k' = 768. BM=BN=128, BK=64.
// smem tiles 128 rows x 64 halfs (128B rows); Swizzle<3,3,3>: 16B chunk c at
// row r stored at chunk (c ^ (r&7)) -> LDSM x4 is conflict-free (4 wf).
// 8 warps: warp grid 2(m) x 4(n), warp tile 64x32, mma m16n8k16, 4 k16/tile.
#define BKB 64
#define TILE_H (128 * 64)            // halfs per tile buffer

template <int EPI>
__global__ void __launch_bounds__(256, 2) gemm_f16(
    const __half* __restrict__ Aext, const __half* __restrict__ Wext,
    const float* __restrict__ bias, const float* __restrict__ pos_enc,
    float* __restrict__ Cout)
{
    extern __shared__ __half smh[];
    __half* Asm = smh;                    // [2][128][64]
    __half* Bsm = smh + 2 * TILE_H;       // [2][128][64]

    const int tid  = threadIdx.x;
    const int lane = tid & 31;
    const int warp = tid >> 5;
    const int wm = warp >> 2;      // 0..1
    const int wn = warp & 3;       // 0..3
    const int bm = blockIdx.y * 128;
    const int bn = blockIdx.x * 128;

    // loader coords: 1024 chunks per matrix, 4 per thread
    int lrow[4], lc8[4];
#pragma unroll
    for (int l = 0; l < 4; l++) {
        int idx = tid + l * 256;
        lrow[l] = idx >> 3;
        lc8[l]  = idx & 7;
    }

    auto issue_tile = [&](int t) {
        const int buf = t & 1;
        const int ko = t * BKB;
        __half* Ab = Asm + buf * TILE_H;
        __half* Bb = Bsm + buf * TILE_H;
#pragma unroll
        for (int l = 0; l < 4; l++) {
            int row = lrow[l], c8 = lc8[l];
            int pc = ((c8 ^ (row & 7)) << 3);
            uint32_t da = (uint32_t)__cvta_generic_to_shared(Ab + row * 64 + pc);
            CP_ASYNC_16(da, &Aext[(size_t)(bm + row) * KEXT + ko + c8 * 8]);
            uint32_t db = (uint32_t)__cvta_generic_to_shared(Bb + row * 64 + pc);
            CP_ASYNC_16(db, &Wext[(size_t)(bn + row) * KEXT + ko + c8 * 8]);
        }
        CP_ASYNC_COMMIT();
    };

    float acc[4][4][4];
#pragma unroll
    for (int mt = 0; mt < 4; mt++)
#pragma unroll
        for (int nt = 0; nt < 4; nt++)
#pragma unroll
            for (int e = 0; e < 4; e++) acc[mt][nt][e] = 0.f;

    issue_tile(0);

    const int nkt = KEXT / BKB;   // 12
    for (int kt = 0; kt < nkt; kt++) {
        const int cur = kt & 1;
        if (kt + 1 < nkt) {
            issue_tile(kt + 1);
            CP_ASYNC_WAIT(1);      // tile kt complete (kt+1 may be in flight)
        } else {
            CP_ASYNC_WAIT(0);
        }
        __syncthreads();

        const __half* Ab = Asm + cur * TILE_H;
        const __half* Bb = Bsm + cur * TILE_H;
#pragma unroll
        for (int s = 0; s < 4; s++) {       // four k16 steps
            uint32_t a[4][4];
#pragma unroll
            for (int mt = 0; mt < 4; mt++) {
                int r = wm * 64 + mt * 16 + (lane & 15);
                int ch = 2 * s + (lane >> 4);
                uint32_t ad = (uint32_t)__cvta_generic_to_shared(
                    Ab + r * 64 + ((ch ^ (r & 7)) << 3));
                LDSM_X4(a[mt][0], a[mt][1], a[mt][2], a[mt][3], ad);
            }
            uint32_t b[4][2];
#pragma unroll
            for (int nt2 = 0; nt2 < 2; nt2++) {
                int r = wn * 32 + nt2 * 16 + ((lane >> 4) << 3) + (lane & 7);
                int ch = 2 * s + ((lane >> 3) & 1);
                uint32_t ad = (uint32_t)__cvta_generic_to_shared(
                    Bb + r * 64 + ((ch ^ (r & 7)) << 3));
                LDSM_X4(b[nt2 * 2][0], b[nt2 * 2][1],
                        b[nt2 * 2 + 1][0], b[nt2 * 2 + 1][1], ad);
            }
#pragma unroll
            for (int mt = 0; mt < 4; mt++)
#pragma unroll
                for (int nt = 0; nt < 4; nt++)
                    MMA_F16(acc[mt][nt], a[mt], b[nt][0], b[nt][1]);
        }
        __syncthreads();
    }

    // ---- epilogue ----
    if (EPI == 0) {
#pragma unroll
        for (int mt = 0; mt < 4; mt++) {
            int m0 = bm + wm * 64 + mt * 16 + (lane >> 2);
#pragma unroll
            for (int nt = 0; nt < 4; nt++) {
                int n0 = bn + wn * 32 + nt * 8 + (lane & 3) * 2;
#pragma unroll
                for (int e = 0; e < 4; e++) {
                    int m = m0 + (e >> 1) * 8;
                    int n = n0 + (e & 1);
                    int b = m >> 8;
                    int i = m & 255;
                    float val = acc[mt][nt][e] + bias[n];
                    int region = n / DIMC;
                    int ch = n - region * DIMC;
                    int h = ch >> 5;
                    int d = ch & 31;
                    size_t dst = ((size_t)(b * HEADS + h) * NTOK + i) * HD + d;
                    if (region == 0) {
                        g_q[dst] = fmaxf(val, 0.f);
                    } else if (region == 1) {
                        g_k[dst] = fmaxf(val + pos_enc[(size_t)i * DIMC + ch], 0.f);
                    } else {
                        g_v[dst] = val;
                    }
                }
            }
        }
    } else {
#pragma unroll
        for (int mt = 0; mt < 4; mt++) {
            int m0 = bm + wm * 64 + mt * 16 + (lane >> 2);
#pragma unroll
            for (int nt = 0; nt < 4; nt++) {
                int n0 = bn + wn * 32 + nt * 8 + (lane & 3) * 2;
                float2 lo, hi2;
                lo.x  = acc[mt][nt][0] + bias[n0];
                lo.y  = acc[mt][nt][1] + bias[n0 + 1];
                hi2.x = acc[mt][nt][2] + bias[n0];
                hi2.y = acc[mt][nt][3] + bias[n0 + 1];
                *(float2*)&Cout[(size_t)m0 * DIMC + n0] = lo;
                *(float2*)&Cout[(size_t)(m0 + 8) * DIMC + n0] = hi2;
            }
        }
    }
}
#define GEMM_SMEM (4 * TILE_H * 2)   // 65536 bytes

// ---------------- fused linear attention + depthwise conv (R14 proven) -----
#define AT_KS    0                      // k p32: 256*32 = 8192
#define AT_VS32  8192                   // v p32: 8192
#define AT_VS33  16384                  // v p33: 256*33 = 8448
#define AT_KVF   24832                  // kv: 32*36 = 1152
#define AT_KSUM  25984                  // 32
#define AT_WS    26016                  // wst[tap][d]: 800
#define AT_BS    26816                  // 32
#define AT_FLOATS 26848
#define AT_BYTES (AT_FLOATS * 4)        // 107392 bytes -> 2 CTAs/SM

__global__ void __launch_bounds__(256, 2) attn_kernel(
    const float* __restrict__ dwc_w, const float* __restrict__ dwc_b)
{
    extern __shared__ float sm[];
    float* ks32 = sm + AT_KS;
    float* vs32 = sm + AT_VS32;
    float* vs33 = sm + AT_VS33;
    float* kvf  = sm + AT_KVF;
    float* ksum = sm + AT_KSUM;
    float* wst  = sm + AT_WS;
    float* bsm  = sm + AT_BS;
    float* part = sm;                   // overlay: [8][32][33], post-phase1

    const int tid = threadIdx.x;
    const int bh = blockIdx.x;
    const size_t base = (size_t)bh * (NTOK * HD);

    for (int idx = tid; idx < 2048; idx += 256) {
        int row = idx >> 3;
        int col = (idx & 7) * 4;
        float4 t = *(const float4*)&g_k[base + row * 32 + col];
        *(float4*)&ks32[row * 32 + col] = t;
        t = *(const float4*)&g_v[base + row * 32 + col];
        *(float4*)&vs32[row * 32 + col] = t;
        vs33[row * 33 + col + 0] = t.x;
        vs33[row * 33 + col + 1] = t.y;
        vs33[row * 33 + col + 2] = t.z;
        vs33[row * 33 + col + 3] = t.w;
    }
    for (int idx = tid; idx < 800; idx += 256)
        wst[idx] = dwc_w[(idx & 31) * 25 + (idx >> 5)];
    if (tid < 32) bsm[tid] = dwc_b[tid];
    __syncthreads();

    // phase 1: per-warp partial kv over j-slice; lane = c owns all 32 d
    {
        const int w = tid >> 5;
        const int lane = tid & 31;
        float pacc[32];
#pragma unroll
        for (int d = 0; d < 32; d++) pacc[d] = 0.f;
        float psum = 0.f;
        const int j0 = w * 32;
#pragma unroll 4
        for (int jj = 0; jj < 32; jj++) {
            int j = j0 + jj;
            float kc = ks32[j * 32 + lane];
            psum += kc;
#pragma unroll
            for (int dq = 0; dq < 8; dq++) {
                float4 v4 = *(const float4*)&vs32[j * 32 + dq * 4];
                pacc[dq * 4 + 0] += kc * v4.x;
                pacc[dq * 4 + 1] += kc * v4.y;
                pacc[dq * 4 + 2] += kc * v4.z;
                pacc[dq * 4 + 3] += kc * v4.w;
            }
        }
        __syncthreads();
        float* pw = part + w * 1056 + lane * 33;
#pragma unroll
        for (int d = 0; d < 32; d++) pw[d] = pacc[d];
        pw[32] = psum;
    }
    __syncthreads();

    // reduce partials -> kvf (pitch 36) + ksum
    {
        const int c  = tid >> 3;
        const int d0 = (tid & 7) * 4;
        float r0 = 0.f, r1 = 0.f, r2 = 0.f, r3 = 0.f;
#pragma unroll
        for (int w = 0; w < 8; w++) {
            const float* p = part + w * 1056 + c * 33 + d0;
            r0 += p[0]; r1 += p[1]; r2 += p[2]; r3 += p[3];
        }
        float4 o; o.x = r0; o.y = r1; o.z = r2; o.w = r3;
        *(float4*)&kvf[c * 36 + d0] = o;
        if ((tid & 7) == 0) {
            float s = 0.f;
#pragma unroll
            for (int w = 0; w < 8; w++) s += part[w * 1056 + c * 33 + 32];
            ksum[c] = s;
        }
    }
    __syncthreads();

    // phase 2: per-token output
    const int i = tid;
    float qr[32];
#pragma unroll
    for (int j2 = 0; j2 < 8; j2++)
        *(float4*)&qr[j2 * 4] = *(const float4*)&g_q[base + (size_t)i * 32 + j2 * 4];

    float zden = EPS;
#pragma unroll
    for (int c = 0; c < 32; c++) zden += qr[c] * ksum[c];
    const float z = 1.0f / zden;

    float acc[32];
#pragma unroll
    for (int d = 0; d < 32; d++) acc[d] = 0.f;
#pragma unroll
    for (int c = 0; c < 32; c++) {
        float qc = qr[c];
#pragma unroll
        for (int dq = 0; dq < 8; dq++) {
            float4 kv4 = *(const float4*)&kvf[c * 36 + dq * 4];
            acc[dq * 4 + 0] += qc * kv4.x;
            acc[dq * 4 + 1] += qc * kv4.y;
            acc[dq * 4 + 2] += qc * kv4.z;
            acc[dq * 4 + 3] += qc * kv4.w;
        }
    }
#pragma unroll
    for (int d = 0; d < 32; d++) acc[d] *= z;

    const int a = i >> 4;
    const int b_s = i & 15;
#pragma unroll
    for (int ka = 0; ka < KWIN; ka++) {
        int aa = a + ka - 2;
        if (aa < 0 || aa > 15) continue;
#pragma unroll
        for (int kb = 0; kb < KWIN; kb++) {
            int bb = b_s + kb - 2;
            if (bb < 0 || bb > 15) continue;
            int nn = aa * 16 + bb;
            int koff = ka * KWIN + kb;
#pragma unroll
            for (int dq = 0; dq < 8; dq++) {
                float4 w4 = *(const float4*)&wst[koff * 32 + dq * 4];
                acc[dq * 4 + 0] += vs33[nn * 33 + dq * 4 + 0] * w4.x;
                acc[dq * 4 + 1] += vs33[nn * 33 + dq * 4 + 1] * w4.y;
                acc[dq * 4 + 2] += vs33[nn * 33 + dq * 4 + 2] * w4.z;
                acc[dq * 4 + 3] += vs33[nn * 33 + dq * 4 + 3] * w4.w;
            }
        }
    }
#pragma unroll
    for (int d = 0; d < 32; d++) acc[d] += bsm[d];

    // epilogue: fp16 hi/lo split -> g_ae extended row for proj GEMM
    const int b = bh / HEADS;
    const int h = bh - b * HEADS;
    __half hbuf[32], lbuf[32];
#pragma unroll
    for (int d = 0; d < 32; d++) {
        hbuf[d] = __float2half(acc[d]);
        lbuf[d] = __float2half(acc[d] - __half2float(hbuf[d]));
    }
    __half* dst = g_ae + ((size_t)(b * NTOK + i)) * KEXT + h * HD;
#pragma unroll
    for (int j = 0; j < 4; j++) {
        uint4 hp = ((const uint4*)hbuf)[j];
        uint4 lp = ((const uint4*)lbuf)[j];
        *(uint4*)&dst[j * 8]        = hp;   // seg 0: hi
        *(uint4*)&dst[DIMC + j * 8] = lp;   // seg 1: lo
    }
}

// ---------------- launch ----------------------------------------------------
extern "C" void kernel_launch(void* const* d_in, const int* in_sizes, int n_in,
                              void* d_out, int out_size)
{
    const float* x       = (const float*)d_in[0];
    const float* qkv_w   = (const float*)d_in[1];
    const float* qkv_b   = (const float*)d_in[2];
    const float* pos_enc = (const float*)d_in[3];
    const float* dwc_w   = (const float*)d_in[4];
    const float* dwc_b   = (const float*)d_in[5];
    const float* proj_w  = (const float*)d_in[6];
    const float* proj_b  = (const float*)d_in[7];
    float* out = (float*)d_out;

    cudaFuncSetAttribute(attn_kernel,
                         cudaFuncAttributeMaxDynamicSharedMemorySize, AT_BYTES);
    cudaFuncSetAttribute(gemm_f16<0>,
                         cudaFuncAttributeMaxDynamicSharedMemorySize, GEMM_SMEM);
    cudaFuncSetAttribute(gemm_f16<1>,
                         cudaFuncAttributeMaxDynamicSharedMemorySize, GEMM_SMEM);

    __half* ae; cudaGetSymbolAddress((void**)&ae, g_ae);
    __half* we; cudaGetSymbolAddress((void**)&we, g_we);
    __half* pe; cudaGetSymbolAddress((void**)&pe, g_pe);

    // 0) conversions: x -> [hi|lo], qkv_w/proj_w -> [hi|hi]
    {
        int nq = MTOT * DIMC / 4;
        cvt_A_ext<<<(nq + 255) / 256, 256>>>(x, ae, nq);
        int nw = 3 * DIMC * DIMC / 4;
        cvt_W_ext<<<(nw + 255) / 256, 256>>>(qkv_w, we, nw);
        int np = DIMC * DIMC / 4;
        cvt_W_ext<<<(np + 255) / 256, 256>>>(proj_w, pe, np);
    }

    // 1) qkv GEMM (fp16 TC) + fused epilogue -> g_q/g_k/g_v
    gemm_f16<0><<<dim3((3 * DIMC) / 128, MTOT / 128), 256, GEMM_SMEM>>>(
        ae, we, qkv_b, pos_enc, nullptr);

    // 2) fused linear attention + depthwise conv -> y_ext (reuses g_ae)
    attn_kernel<<<BHTOT, 256, AT_BYTES>>>(dwc_w, dwc_b);

    // 3) proj GEMM (fp16 TC) -> out
    gemm_f16<1><<<dim3(DIMC / 128, MTOT / 128), 256, GEMM_SMEM>>>(
        ae, pe, proj_b, nullptr, out);
}

// round 16
// speedup vs baseline: 2.1216x; 1.2855x over previous
#include <cuda_runtime.h>
#include <cuda_fp16.h>
#include <cstddef>
#include <cstdint>

#define DIMC   384
#define HEADS  12
#define HD     32
#define NTOK   256
#define BATCH  256
#define BHTOT  (BATCH * HEADS)      // 3072
#define MTOT   (BATCH * NTOK)       // 65536
#define KWIN   5
#define EPS    1e-6f

// ---------------- scratch (device globals: allocation-free) ----------------
__device__ float g_q[(size_t)BHTOT * NTOK * HD];
__device__ float g_k[(size_t)BHTOT * NTOK * HD];
__device__ float g_v[(size_t)BHTOT * NTOK * HD];

__device__ __half g_ae[(size_t)MTOT * DIMC];        // x_f16 then y_f16
__device__ __half g_we[(size_t)(3 * DIMC) * DIMC];  // qkv_w f16
__device__ __half g_pe[(size_t)DIMC * DIMC];        // proj_w f16

// ---------------- PTX helpers ----------------------------------------------
#define LDSM_X4(r0, r1, r2, r3, addr) \
    asm volatile("ldmatrix.sync.aligned.m8n8.x4.shared.b16 {%0,%1,%2,%3}, [%4];" \
        : "=r"(r0), "=r"(r1), "=r"(r2), "=r"(r3) : "r"(addr))

#define MMA_F16(c, a, b0, b1) \
    asm volatile("mma.sync.aligned.m16n8k16.row.col.f32.f16.f16.f32 " \
        "{%0,%1,%2,%3}, {%4,%5,%6,%7}, {%8,%9}, {%0,%1,%2,%3};" \
        : "+f"(c[0]), "+f"(c[1]), "+f"(c[2]), "+f"(c[3]) \
        : "r"(a[0]), "r"(a[1]), "r"(a[2]), "r"(a[3]), "r"(b0), "r"(b1))

#define CP_ASYNC_16(smem_u32, gptr) \
    asm volatile("cp.async.cg.shared.global [%0], [%1], 16;" \
        :: "r"(smem_u32), "l"(gptr))
#define CP_ASYNC_COMMIT() asm volatile("cp.async.commit_group;" ::: "memory")
#define CP_ASYNC_WAIT(N)  asm volatile("cp.async.wait_group %0;" :: "n"(N) : "memory")

// ---------------- elementwise fp32 -> fp16 ----------------------------------
__global__ void __launch_bounds__(256) cvt_half(
    const float* __restrict__ src, __half* __restrict__ dst, int nquads)
{
    int i = blockIdx.x * blockDim.x + threadIdx.x;
    if (i >= nquads) return;
    float4 v = *(const float4*)&src[(size_t)i * 4];
    uint2 hp;
    ((__half*)&hp)[0] = __float2half(v.x);
    ((__half*)&hp)[1] = __float2half(v.y);
    ((__half*)&hp)[2] = __float2half(v.z);
    ((__half*)&hp)[3] = __float2half(v.w);
    *(uint2*)&dst[(size_t)i * 4] = hp;
}

// ---------------- fp16 tensor-core GEMM (BK=64, XOR-swizzled, cp.async) -----
// C[m][n] = sum_k A[m][k] * W[n][k], K = 384. BM=BN=128, BK=64, 6 k-tiles.
// smem tiles 128 x 64 halfs (128B rows); Swizzle<3,3,3>: 16B chunk c at row r
// stored at chunk (c ^ (r&7)) -> conflict-free LDSM (4 wf per x4).
// 8 warps: warp grid 2(m) x 4(n), warp tile 64x32, mma m16n8k16.
#define BKB 64
#define TILE_H (128 * 64)

template <int EPI>
__global__ void __launch_bounds__(256, 2) gemm_f16(
    const __half* __restrict__ Aext, const __half* __restrict__ Wext,
    const float* __restrict__ bias, const float* __restrict__ pos_enc,
    float* __restrict__ Cout)
{
    extern __shared__ __half smh[];
    __half* Asm = smh;                    // [2][128][64]
    __half* Bsm = smh + 2 * TILE_H;       // [2][128][64]

    const int tid  = threadIdx.x;
    const int lane = tid & 31;
    const int warp = tid >> 5;
    const int wm = warp >> 2;      // 0..1
    const int wn = warp & 3;       // 0..3
    const int bm = blockIdx.y * 128;
    const int bn = blockIdx.x * 128;

    int lrow[4], lc8[4];
#pragma unroll
    for (int l = 0; l < 4; l++) {
        int idx = tid + l * 256;
        lrow[l] = idx >> 3;
        lc8[l]  = idx & 7;
    }

    auto issue_tile = [&](int t) {
        const int buf = t & 1;
        const int ko = t * BKB;
        __half* Ab = Asm + buf * TILE_H;
        __half* Bb = Bsm + buf * TILE_H;
#pragma unroll
        for (int l = 0; l < 4; l++) {
            int row = lrow[l], c8 = lc8[l];
            int pc = ((c8 ^ (row & 7)) << 3);
            uint32_t da = (uint32_t)__cvta_generic_to_shared(Ab + row * 64 + pc);
            CP_ASYNC_16(da, &Aext[(size_t)(bm + row) * DIMC + ko + c8 * 8]);
            uint32_t db = (uint32_t)__cvta_generic_to_shared(Bb + row * 64 + pc);
            CP_ASYNC_16(db, &Wext[(size_t)(bn + row) * DIMC + ko + c8 * 8]);
        }
        CP_ASYNC_COMMIT();
    };

    float acc[4][4][4];
#pragma unroll
    for (int mt = 0; mt < 4; mt++)
#pragma unroll
        for (int nt = 0; nt < 4; nt++)
#pragma unroll
            for (int e = 0; e < 4; e++) acc[mt][nt][e] = 0.f;

    issue_tile(0);

    const int nkt = DIMC / BKB;   // 6
    for (int kt = 0; kt < nkt; kt++) {
        const int cur = kt & 1;
        if (kt + 1 < nkt) {
            issue_tile(kt + 1);
            CP_ASYNC_WAIT(1);
        } else {
            CP_ASYNC_WAIT(0);
        }
        __syncthreads();

        const __half* Ab = Asm + cur * TILE_H;
        const __half* Bb = Bsm + cur * TILE_H;
#pragma unroll
        for (int s = 0; s < 4; s++) {       // four k16 steps
            uint32_t a[4][4];
#pragma unroll
            for (int mt = 0; mt < 4; mt++) {
                int r = wm * 64 + mt * 16 + (lane & 15);
                int ch = 2 * s + (lane >> 4);
                uint32_t ad = (uint32_t)__cvta_generic_to_shared(
                    Ab + r * 64 + ((ch ^ (r & 7)) << 3));
                LDSM_X4(a[mt][0], a[mt][1], a[mt][2], a[mt][3], ad);
            }
            uint32_t b[4][2];
#pragma unroll
            for (int nt2 = 0; nt2 < 2; nt2++) {
                int r = wn * 32 + nt2 * 16 + ((lane >> 4) << 3) + (lane & 7);
                int ch = 2 * s + ((lane >> 3) & 1);
                uint32_t ad = (uint32_t)__cvta_generic_to_shared(
                    Bb + r * 64 + ((ch ^ (r & 7)) << 3));
                LDSM_X4(b[nt2 * 2][0], b[nt2 * 2][1],
                        b[nt2 * 2 + 1][0], b[nt2 * 2 + 1][1], ad);
            }
#pragma unroll
            for (int mt = 0; mt < 4; mt++)
#pragma unroll
                for (int nt = 0; nt < 4; nt++)
                    MMA_F16(acc[mt][nt], a[mt], b[nt][0], b[nt][1]);
        }
        __syncthreads();
    }

    // ---- epilogue ----
    if (EPI == 0) {
#pragma unroll
        for (int mt = 0; mt < 4; mt++) {
            int m0 = bm + wm * 64 + mt * 16 + (lane >> 2);
#pragma unroll
            for (int nt = 0; nt < 4; nt++) {
                int n0 = bn + wn * 32 + nt * 8 + (lane & 3) * 2;
#pragma unroll
                for (int e = 0; e < 4; e++) {
                    int m = m0 + (e >> 1) * 8;
                    int n = n0 + (e & 1);
                    int b = m >> 8;
                    int i = m & 255;
                    float val = acc[mt][nt][e] + bias[n];
                    int region = n / DIMC;
                    int ch = n - region * DIMC;
                    int h = ch >> 5;
                    int d = ch & 31;
                    size_t dst = ((size_t)(b * HEADS + h) * NTOK + i) * HD + d;
                    if (region == 0) {
                        g_q[dst] = fmaxf(val, 0.f);
                    } else if (region == 1) {
                        g_k[dst] = fmaxf(val + pos_enc[(size_t)i * DIMC + ch], 0.f);
                    } else {
                        g_v[dst] = val;
                    }
                }
            }
        }
    } else {
#pragma unroll
        for (int mt = 0; mt < 4; mt++) {
            int m0 = bm + wm * 64 + mt * 16 + (lane >> 2);
#pragma unroll
            for (int nt = 0; nt < 4; nt++) {
                int n0 = bn + wn * 32 + nt * 8 + (lane & 3) * 2;
                float2 lo, hi2;
                lo.x  = acc[mt][nt][0] + bias[n0];
                lo.y  = acc[mt][nt][1] + bias[n0 + 1];
                hi2.x = acc[mt][nt][2] + bias[n0];
                hi2.y = acc[mt][nt][3] + bias[n0 + 1];
                *(float2*)&Cout[(size_t)m0 * DIMC + n0] = lo;
                *(float2*)&Cout[(size_t)(m0 + 8) * DIMC + n0] = hi2;
            }
        }
    }
}
#define GEMM_SMEM (4 * TILE_H * 2)   // 65536 bytes

// ---------------- fused linear attention + depthwise conv (R14 proven) -----
#define AT_KS    0                      // k p32: 256*32 = 8192
#define AT_VS32  8192                   // v p32: 8192
#define AT_VS33  16384                  // v p33: 256*33 = 8448
#define AT_KVF   24832                  // kv: 32*36 = 1152
#define AT_KSUM  25984                  // 32
#define AT_WS    26016                  // wst[tap][d]: 800
#define AT_BS    26816                  // 32
#define AT_FLOATS 26848
#define AT_BYTES (AT_FLOATS * 4)        // 107392 bytes -> 2 CTAs/SM

__global__ void __launch_bounds__(256, 2) attn_kernel(
    const float* __restrict__ dwc_w, const float* __restrict__ dwc_b)
{
    extern __shared__ float sm[];
    float* ks32 = sm + AT_KS;
    float* vs32 = sm + AT_VS32;
    float* vs33 = sm + AT_VS33;
    float* kvf  = sm + AT_KVF;
    float* ksum = sm + AT_KSUM;
    float* wst  = sm + AT_WS;
    float* bsm  = sm + AT_BS;
    float* part = sm;                   // overlay: [8][32][33], post-phase1

    const int tid = threadIdx.x;
    const int bh = blockIdx.x;
    const size_t base = (size_t)bh * (NTOK * HD);

    for (int idx = tid; idx < 2048; idx += 256) {
        int row = idx >> 3;
        int col = (idx & 7) * 4;
        float4 t = *(const float4*)&g_k[base + row * 32 + col];
        *(float4*)&ks32[row * 32 + col] = t;
        t = *(const float4*)&g_v[base + row * 32 + col];
        *(float4*)&vs32[row * 32 + col] = t;
        vs33[row * 33 + col + 0] = t.x;
        vs33[row * 33 + col + 1] = t.y;
        vs33[row * 33 + col + 2] = t.z;
        vs33[row * 33 + col + 3] = t.w;
    }
    for (int idx = tid; idx < 800; idx += 256)
        wst[idx] = dwc_w[(idx & 31) * 25 + (idx >> 5)];
    if (tid < 32) bsm[tid] = dwc_b[tid];
    __syncthreads();

    // phase 1: per-warp partial kv over j-slice; lane = c owns all 32 d
    {
        const int w = tid >> 5;
        const int lane = tid & 31;
        float pacc[32];
#pragma unroll
        for (int d = 0; d < 32; d++) pacc[d] = 0.f;
        float psum = 0.f;
        const int j0 = w * 32;
#pragma unroll 4
        for (int jj = 0; jj < 32; jj++) {
            int j = j0 + jj;
            float kc = ks32[j * 32 + lane];
            psum += kc;
#pragma unroll
            for (int dq = 0; dq < 8; dq++) {
                float4 v4 = *(const float4*)&vs32[j * 32 + dq * 4];
                pacc[dq * 4 + 0] += kc * v4.x;
                pacc[dq * 4 + 1] += kc * v4.y;
                pacc[dq * 4 + 2] += kc * v4.z;
                pacc[dq * 4 + 3] += kc * v4.w;
            }
        }
        __syncthreads();
        float* pw = part + w * 1056 + lane * 33;
#pragma unroll
        for (int d = 0; d < 32; d++) pw[d] = pacc[d];
        pw[32] = psum;
    }
    __syncthreads();

    // reduce partials -> kvf (pitch 36) + ksum
    {
        const int c  = tid >> 3;
        const int d0 = (tid & 7) * 4;
        float r0 = 0.f, r1 = 0.f, r2 = 0.f, r3 = 0.f;
#pragma unroll
        for (int w = 0; w < 8; w++) {
            const float* p = part + w * 1056 + c * 33 + d0;
            r0 += p[0]; r1 += p[1]; r2 += p[2]; r3 += p[3];
        }
        float4 o; o.x = r0; o.y = r1; o.z = r2; o.w = r3;
        *(float4*)&kvf[c * 36 + d0] = o;
        if ((tid & 7) == 0) {
            float s = 0.f;
#pragma unroll
            for (int w = 0; w < 8; w++) s += part[w * 1056 + c * 33 + 32];
            ksum[c] = s;
        }
    }
    __syncthreads();

    // phase 2: per-token output
    const int i = tid;
    float qr[32];
#pragma unroll
    for (int j2 = 0; j2 < 8; j2++)
        *(float4*)&qr[j2 * 4] = *(const float4*)&g_q[base + (size_t)i * 32 + j2 * 4];

    float zden = EPS;
#pragma unroll
    for (int c = 0; c < 32; c++) zden += qr[c] * ksum[c];
    const float z = 1.0f / zden;

    float acc[32];
#pragma unroll
    for (int d = 0; d < 32; d++) acc[d] = 0.f;
#pragma unroll
    for (int c = 0; c < 32; c++) {
        float qc = qr[c];
#pragma unroll
        for (int dq = 0; dq < 8; dq++) {
            float4 kv4 = *(const float4*)&kvf[c * 36 + dq * 4];
            acc[dq * 4 + 0] += qc * kv4.x;
            acc[dq * 4 + 1] += qc * kv4.y;
            acc[dq * 4 + 2] += qc * kv4.z;
            acc[dq * 4 + 3] += qc * kv4.w;
        }
    }
#pragma unroll
    for (int d = 0; d < 32; d++) acc[d] *= z;

    const int a = i >> 4;
    const int b_s = i & 15;
#pragma unroll
    for (int ka = 0; ka < KWIN; ka++) {
        int aa = a + ka - 2;
        if (aa < 0 || aa > 15) continue;
#pragma unroll
        for (int kb = 0; kb < KWIN; kb++) {
            int bb = b_s + kb - 2;
            if (bb < 0 || bb > 15) continue;
            int nn = aa * 16 + bb;
            int koff = ka * KWIN + kb;
#pragma unroll
            for (int dq = 0; dq < 8; dq++) {
                float4 w4 = *(const float4*)&wst[koff * 32 + dq * 4];
                acc[dq * 4 + 0] += vs33[nn * 33 + dq * 4 + 0] * w4.x;
                acc[dq * 4 + 1] += vs33[nn * 33 + dq * 4 + 1] * w4.y;
                acc[dq * 4 + 2] += vs33[nn * 33 + dq * 4 + 2] * w4.z;
                acc[dq * 4 + 3] += vs33[nn * 33 + dq * 4 + 3] * w4.w;
            }
        }
    }
#pragma unroll
    for (int d = 0; d < 32; d++) acc[d] += bsm[d];

    // epilogue: fp16 convert -> g_ae row segment for proj GEMM
    const int b = bh / HEADS;
    const int h = bh - b * HEADS;
    __half hbuf[32];
#pragma unroll
    for (int d = 0; d < 32; d++) hbuf[d] = __float2half(acc[d]);
    __half* dst = g_ae + ((size_t)(b * NTOK + i)) * DIMC + h * HD;
#pragma unroll
    for (int j = 0; j < 4; j++)
        *(uint4*)&dst[j * 8] = ((const uint4*)hbuf)[j];
}

// ---------------- launch ----------------------------------------------------
extern "C" void kernel_launch(void* const* d_in, const int* in_sizes, int n_in,
                              void* d_out, int out_size)
{
    const float* x       = (const float*)d_in[0];
    const float* qkv_w   = (const float*)d_in[1];
    const float* qkv_b   = (const float*)d_in[2];
    const float* pos_enc = (const float*)d_in[3];
    const float* dwc_w   = (const float*)d_in[4];
    const float* dwc_b   = (const float*)d_in[5];
    const float* proj_w  = (const float*)d_in[6];
    const float* proj_b  = (const float*)d_in[7];
    float* out = (float*)d_out;

    cudaFuncSetAttribute(attn_kernel,
                         cudaFuncAttributeMaxDynamicSharedMemorySize, AT_BYTES);
    cudaFuncSetAttribute(gemm_f16<0>,
                         cudaFuncAttributeMaxDynamicSharedMemorySize, GEMM_SMEM);
    cudaFuncSetAttribute(gemm_f16<1>,
                         cudaFuncAttributeMaxDynamicSharedMemorySize, GEMM_SMEM);

    __half* ae; cudaGetSymbolAddress((void**)&ae, g_ae);
    __half* we; cudaGetSymbolAddress((void**)&we, g_we);
    __half* pe; cudaGetSymbolAddress((void**)&pe, g_pe);

    // 0) conversions: x, qkv_w, proj_w -> fp16 (elementwise)
    {
        int nq = MTOT * DIMC / 4;
        cvt_half<<<(nq + 255) / 256, 256>>>(x, ae, nq);
        int nw = 3 * DIMC * DIMC / 4;
        cvt_half<<<(nw + 255) / 256, 256>>>(qkv_w, we, nw);
        int np = DIMC * DIMC / 4;
        cvt_half<<<(np + 255) / 256, 256>>>(proj_w, pe, np);
    }

    // 1) qkv GEMM (fp16 TC) + fused epilogue -> g_q/g_k/g_v
    gemm_f16<0><<<dim3((3 * DIMC) / 128, MTOT / 128), 256, GEMM_SMEM>>>(
        ae, we, qkv_b, pos_enc, nullptr);

    // 2) fused linear attention + depthwise conv -> y_f16 (reuses g_ae)
    attn_kernel<<<BHTOT, 256, AT_BYTES>>>(dwc_w, dwc_b);

    // 3) proj GEMM (fp16 TC) -> out
    gemm_f16<1><<<dim3(DIMC / 128, MTOT / 128), 256, GEMM_SMEM>>>(
        ae, pe, proj_b, nullptr, out);
}

// round 17
// speedup vs baseline: 2.2782x; 1.0738x over previous
#include <cuda_runtime.h>
#include <cuda_fp16.h>
#include <cstddef>
#include <cstdint>

#define DIMC   384
#define NQKV   (3 * DIMC)           // 1152
#define HEADS  12
#define HD     32
#define NTOK   256
#define BATCH  256
#define BHTOT  (BATCH * HEADS)      // 3072
#define MTOT   (BATCH * NTOK)       // 65536
#define KWIN   5
#define EPS    1e-6f

// ---------------- scratch (device globals: allocation-free) ----------------
__device__ __half g_qkv[(size_t)MTOT * NQKV];       // qkv f16, [m][1152]
__device__ __half g_ae[(size_t)MTOT * DIMC];        // x_f16 then y_f16
__device__ __half g_we[(size_t)NQKV * DIMC];        // qkv_w f16
__device__ __half g_pe[(size_t)DIMC * DIMC];        // proj_w f16

// ---------------- PTX helpers ----------------------------------------------
#define LDSM_X4(r0, r1, r2, r3, addr) \
    asm volatile("ldmatrix.sync.aligned.m8n8.x4.shared.b16 {%0,%1,%2,%3}, [%4];" \
        : "=r"(r0), "=r"(r1), "=r"(r2), "=r"(r3) : "r"(addr))

#define MMA_F16(c, a, b0, b1) \
    asm volatile("mma.sync.aligned.m16n8k16.row.col.f32.f16.f16.f32 " \
        "{%0,%1,%2,%3}, {%4,%5,%6,%7}, {%8,%9}, {%0,%1,%2,%3};" \
        : "+f"(c[0]), "+f"(c[1]), "+f"(c[2]), "+f"(c[3]) \
        : "r"(a[0]), "r"(a[1]), "r"(a[2]), "r"(a[3]), "r"(b0), "r"(b1))

#define CP_ASYNC_16(smem_u32, gptr) \
    asm volatile("cp.async.cg.shared.global [%0], [%1], 16;" \
        :: "r"(smem_u32), "l"(gptr))
#define CP_ASYNC_COMMIT() asm volatile("cp.async.commit_group;" ::: "memory")
#define CP_ASYNC_WAIT(N)  asm volatile("cp.async.wait_group %0;" :: "n"(N) : "memory")

__device__ __forceinline__ void h8_to_f(uint4 u, float* f) {
    float2 t;
    t = __half22float2(*(const __half2*)&u.x); f[0] = t.x; f[1] = t.y;
    t = __half22float2(*(const __half2*)&u.y); f[2] = t.x; f[3] = t.y;
    t = __half22float2(*(const __half2*)&u.z); f[4] = t.x; f[5] = t.y;
    t = __half22float2(*(const __half2*)&u.w); f[6] = t.x; f[7] = t.y;
}

// ---------------- elementwise fp32 -> fp16 ----------------------------------
__global__ void __launch_bounds__(256) cvt_half(
    const float* __restrict__ src, __half* __restrict__ dst, int nquads)
{
    int i = blockIdx.x * blockDim.x + threadIdx.x;
    if (i >= nquads) return;
    float4 v = *(const float4*)&src[(size_t)i * 4];
    uint2 hp;
    ((__half*)&hp)[0] = __float2half(v.x);
    ((__half*)&hp)[1] = __float2half(v.y);
    ((__half*)&hp)[2] = __float2half(v.z);
    ((__half*)&hp)[3] = __float2half(v.w);
    *(uint2*)&dst[(size_t)i * 4] = hp;
}

// ---------------- fp16 tensor-core GEMM (BK=64, XOR-swizzled, cp.async) -----
// C[m][n] = sum_k A[m][k] * W[n][k], K = 384. BM=BN=128, BK=64, 6 k-tiles.
// Swizzle<3,3,3>: 16B chunk c at row r stored at chunk (c ^ (r&7)).
// 8 warps: warp grid 2(m) x 4(n), warp tile 64x32, mma m16n8k16.
// EPI=0: qkv epilogue -> fp16 [m][1152] coalesced (bias, relu, +pos_enc)
// EPI=1: proj epilogue -> fp32 out (bias)
#define BKB 64
#define TILE_H (128 * 64)

template <int EPI>
__global__ void __launch_bounds__(256, 2) gemm_f16(
    const __half* __restrict__ Aext, const __half* __restrict__ Wext,
    const float* __restrict__ bias, const float* __restrict__ pos_enc,
    float* __restrict__ Cout)
{
    extern __shared__ __half smh[];
    __half* Asm = smh;                    // [2][128][64]
    __half* Bsm = smh + 2 * TILE_H;       // [2][128][64]

    const int tid  = threadIdx.x;
    const int lane = tid & 31;
    const int warp = tid >> 5;
    const int wm = warp >> 2;      // 0..1
    const int wn = warp & 3;       // 0..3
    const int bm = blockIdx.y * 128;
    const int bn = blockIdx.x * 128;

    int lrow[4], lc8[4];
#pragma unroll
    for (int l = 0; l < 4; l++) {
        int idx = tid + l * 256;
        lrow[l] = idx >> 3;
        lc8[l]  = idx & 7;
    }

    auto issue_tile = [&](int t) {
        const int buf = t & 1;
        const int ko = t * BKB;
        __half* Ab = Asm + buf * TILE_H;
        __half* Bb = Bsm + buf * TILE_H;
#pragma unroll
        for (int l = 0; l < 4; l++) {
            int row = lrow[l], c8 = lc8[l];
            int pc = ((c8 ^ (row & 7)) << 3);
            uint32_t da = (uint32_t)__cvta_generic_to_shared(Ab + row * 64 + pc);
            CP_ASYNC_16(da, &Aext[(size_t)(bm + row) * DIMC + ko + c8 * 8]);
            uint32_t db = (uint32_t)__cvta_generic_to_shared(Bb + row * 64 + pc);
            CP_ASYNC_16(db, &Wext[(size_t)(bn + row) * DIMC + ko + c8 * 8]);
        }
        CP_ASYNC_COMMIT();
    };

    float acc[4][4][4];
#pragma unroll
    for (int mt = 0; mt < 4; mt++)
#pragma unroll
        for (int nt = 0; nt < 4; nt++)
#pragma unroll
            for (int e = 0; e < 4; e++) acc[mt][nt][e] = 0.f;

    issue_tile(0);

    const int nkt = DIMC / BKB;   // 6
    for (int kt = 0; kt < nkt; kt++) {
        const int cur = kt & 1;
        if (kt + 1 < nkt) {
            issue_tile(kt + 1);
            CP_ASYNC_WAIT(1);
        } else {
            CP_ASYNC_WAIT(0);
        }
        __syncthreads();

        const __half* Ab = Asm + cur * TILE_H;
        const __half* Bb = Bsm + cur * TILE_H;
#pragma unroll
        for (int s = 0; s < 4; s++) {       // four k16 steps
            uint32_t a[4][4];
#pragma unroll
            for (int mt = 0; mt < 4; mt++) {
                int r = wm * 64 + mt * 16 + (lane & 15);
                int ch = 2 * s + (lane >> 4);
                uint32_t ad = (uint32_t)__cvta_generic_to_shared(
                    Ab + r * 64 + ((ch ^ (r & 7)) << 3));
                LDSM_X4(a[mt][0], a[mt][1], a[mt][2], a[mt][3], ad);
            }
            uint32_t b[4][2];
#pragma unroll
            for (int nt2 = 0; nt2 < 2; nt2++) {
                int r = wn * 32 + nt2 * 16 + ((lane >> 4) << 3) + (lane & 7);
                int ch = 2 * s + ((lane >> 3) & 1);
                uint32_t ad = (uint32_t)__cvta_generic_to_shared(
                    Bb + r * 64 + ((ch ^ (r & 7)) << 3));
                LDSM_X4(b[nt2 * 2][0], b[nt2 * 2][1],
                        b[nt2 * 2 + 1][0], b[nt2 * 2 + 1][1], ad);
            }
#pragma unroll
            for (int mt = 0; mt < 4; mt++)
#pragma unroll
                for (int nt = 0; nt < 4; nt++)
                    MMA_F16(acc[mt][nt], a[mt], b[nt][0], b[nt][1]);
        }
        __syncthreads();
    }

    // ---- epilogue ----
    if (EPI == 0) {
        // fp16 coalesced store to g_qkv[m][1152]; bias + relu/pos per region
#pragma unroll
        for (int mt = 0; mt < 4; mt++) {
            int m0 = bm + wm * 64 + mt * 16 + (lane >> 2);
#pragma unroll
            for (int nt = 0; nt < 4; nt++) {
                int n0 = bn + wn * 32 + nt * 8 + (lane & 3) * 2;
                int region = n0 / DIMC;          // n0 even -> pair same region
                int ch0 = n0 - region * DIMC;
                float b0 = bias[n0], b1 = bias[n0 + 1];
#pragma unroll
                for (int ep = 0; ep < 2; ep++) {
                    int m = m0 + ep * 8;
                    int i = m & 255;
                    float v0 = acc[mt][nt][ep * 2 + 0] + b0;
                    float v1 = acc[mt][nt][ep * 2 + 1] + b1;
                    if (region == 0) {
                        v0 = fmaxf(v0, 0.f); v1 = fmaxf(v1, 0.f);
                    } else if (region == 1) {
                        v0 = fmaxf(v0 + pos_enc[(size_t)i * DIMC + ch0], 0.f);
                        v1 = fmaxf(v1 + pos_enc[(size_t)i * DIMC + ch0 + 1], 0.f);
                    }
                    __half2 h = __floats2half2_rn(v0, v1);
                    *(__half2*)&g_qkv[(size_t)m * NQKV + n0] = h;
                }
            }
        }
    } else {
#pragma unroll
        for (int mt = 0; mt < 4; mt++) {
            int m0 = bm + wm * 64 + mt * 16 + (lane >> 2);
#pragma unroll
            for (int nt = 0; nt < 4; nt++) {
                int n0 = bn + wn * 32 + nt * 8 + (lane & 3) * 2;
                float2 lo, hi2;
                lo.x  = acc[mt][nt][0] + bias[n0];
                lo.y  = acc[mt][nt][1] + bias[n0 + 1];
                hi2.x = acc[mt][nt][2] + bias[n0];
                hi2.y = acc[mt][nt][3] + bias[n0 + 1];
                *(float2*)&Cout[(size_t)m0 * DIMC + n0] = lo;
                *(float2*)&Cout[(size_t)(m0 + 8) * DIMC + n0] = hi2;
            }
        }
    }
}
#define GEMM_SMEM (4 * TILE_H * 2)   // 65536 bytes

// ---------------- fused linear attention + depthwise conv ------------------
// Loads q/k/v slices from g_qkv fp16 [m][1152] (64B row segments), converts
// to fp32 smem; internals identical to the proven R14 kernel.
#define AT_KS    0                      // k p32: 256*32 = 8192
#define AT_VS32  8192                   // v p32: 8192
#define AT_VS33  16384                  // v p33: 256*33 = 8448
#define AT_KVF   24832                  // kv: 32*36 = 1152
#define AT_KSUM  25984                  // 32
#define AT_WS    26016                  // wst[tap][d]: 800
#define AT_BS    26816                  // 32
#define AT_FLOATS 26848
#define AT_BYTES (AT_FLOATS * 4)        // 107392 bytes -> 2 CTAs/SM

__global__ void __launch_bounds__(256, 2) attn_kernel(
    const float* __restrict__ dwc_w, const float* __restrict__ dwc_b)
{
    extern __shared__ float sm[];
    float* ks32 = sm + AT_KS;
    float* vs32 = sm + AT_VS32;
    float* vs33 = sm + AT_VS33;
    float* kvf  = sm + AT_KVF;
    float* ksum = sm + AT_KSUM;
    float* wst  = sm + AT_WS;
    float* bsm  = sm + AT_BS;
    float* part = sm;                   // overlay: [8][32][33], post-phase1

    const int tid = threadIdx.x;
    const int bh = blockIdx.x;
    const int b = bh / HEADS;
    const int h = bh - b * HEADS;
    const int hoff = h * HD;

    // load k, v from g_qkv fp16 (4 threads x uint4 per 32-half row segment)
    for (int idx = tid; idx < 1024; idx += 256) {
        int row = idx >> 2;            // token j
        int c8 = (idx & 3) * 8;        // half offset within segment
        const __half* src = g_qkv + (size_t)(b * NTOK + row) * NQKV + hoff + c8;
        float kf[8], vf[8];
        h8_to_f(*(const uint4*)(src + DIMC), kf);       // k region
        h8_to_f(*(const uint4*)(src + 2 * DIMC), vf);   // v region
#pragma unroll
        for (int j = 0; j < 8; j += 4) {
            *(float4*)&ks32[row * 32 + c8 + j] = *(float4*)&kf[j];
            *(float4*)&vs32[row * 32 + c8 + j] = *(float4*)&vf[j];
        }
#pragma unroll
        for (int j = 0; j < 8; j++) vs33[row * 33 + c8 + j] = vf[j];
    }
    for (int idx = tid; idx < 800; idx += 256)
        wst[idx] = dwc_w[(idx & 31) * 25 + (idx >> 5)];
    if (tid < 32) bsm[tid] = dwc_b[tid];
    __syncthreads();

    // phase 1: per-warp partial kv over j-slice; lane = c owns all 32 d
    {
        const int w = tid >> 5;
        const int lane = tid & 31;
        float pacc[32];
#pragma unroll
        for (int d = 0; d < 32; d++) pacc[d] = 0.f;
        float psum = 0.f;
        const int j0 = w * 32;
#pragma unroll 4
        for (int jj = 0; jj < 32; jj++) {
            int j = j0 + jj;
            float kc = ks32[j * 32 + lane];
            psum += kc;
#pragma unroll
            for (int dq = 0; dq < 8; dq++) {
                float4 v4 = *(const float4*)&vs32[j * 32 + dq * 4];
                pacc[dq * 4 + 0] += kc * v4.x;
                pacc[dq * 4 + 1] += kc * v4.y;
                pacc[dq * 4 + 2] += kc * v4.z;
                pacc[dq * 4 + 3] += kc * v4.w;
            }
        }
        __syncthreads();
        float* pw = part + w * 1056 + lane * 33;
#pragma unroll
        for (int d = 0; d < 32; d++) pw[d] = pacc[d];
        pw[32] = psum;
    }
    __syncthreads();

    // reduce partials -> kvf (pitch 36) + ksum
    {
        const int c  = tid >> 3;
        const int d0 = (tid & 7) * 4;
        float r0 = 0.f, r1 = 0.f, r2 = 0.f, r3 = 0.f;
#pragma unroll
        for (int w = 0; w < 8; w++) {
            const float* p = part + w * 1056 + c * 33 + d0;
            r0 += p[0]; r1 += p[1]; r2 += p[2]; r3 += p[3];
        }
        float4 o; o.x = r0; o.y = r1; o.z = r2; o.w = r3;
        *(float4*)&kvf[c * 36 + d0] = o;
        if ((tid & 7) == 0) {
            float s = 0.f;
#pragma unroll
            for (int w = 0; w < 8; w++) s += part[w * 1056 + c * 33 + 32];
            ksum[c] = s;
        }
    }
    __syncthreads();

    // phase 2: per-token output
    const int i = tid;
    float qr[32];
    {
        const __half* qsrc = g_qkv + (size_t)(b * NTOK + i) * NQKV + hoff;
#pragma unroll
        for (int c8 = 0; c8 < 32; c8 += 8)
            h8_to_f(*(const uint4*)(qsrc + c8), &qr[c8]);
    }

    float zden = EPS;
#pragma unroll
    for (int c = 0; c < 32; c++) zden += qr[c] * ksum[c];
    const float z = 1.0f / zden;

    float acc[32];
#pragma unroll
    for (int d = 0; d < 32; d++) acc[d] = 0.f;
#pragma unroll
    for (int c = 0; c < 32; c++) {
        float qc = qr[c];
#pragma unroll
        for (int dq = 0; dq < 8; dq++) {
            float4 kv4 = *(const float4*)&kvf[c * 36 + dq * 4];
            acc[dq * 4 + 0] += qc * kv4.x;
            acc[dq * 4 + 1] += qc * kv4.y;
            acc[dq * 4 + 2] += qc * kv4.z;
            acc[dq * 4 + 3] += qc * kv4.w;
        }
    }
#pragma unroll
    for (int d = 0; d < 32; d++) acc[d] *= z;

    const int a = i >> 4;
    const int b_s = i & 15;
#pragma unroll
    for (int ka = 0; ka < KWIN; ka++) {
        int aa = a + ka - 2;
        if (aa < 0 || aa > 15) continue;
#pragma unroll
        for (int kb = 0; kb < KWIN; kb++) {
            int bb = b_s + kb - 2;
            if (bb < 0 || bb > 15) continue;
            int nn = aa * 16 + bb;
            int koff = ka * KWIN + kb;
#pragma unroll
            for (int dq = 0; dq < 8; dq++) {
                float4 w4 = *(const float4*)&wst[koff * 32 + dq * 4];
                acc[dq * 4 + 0] += vs33[nn * 33 + dq * 4 + 0] * w4.x;
                acc[dq * 4 + 1] += vs33[nn * 33 + dq * 4 + 1] * w4.y;
                acc[dq * 4 + 2] += vs33[nn * 33 + dq * 4 + 2] * w4.z;
                acc[dq * 4 + 3] += vs33[nn * 33 + dq * 4 + 3] * w4.w;
            }
        }
    }
#pragma unroll
    for (int d = 0; d < 32; d++) acc[d] += bsm[d];

    // epilogue: fp16 convert -> g_ae row segment for proj GEMM
    __half hbuf[32];
#pragma unroll
    for (int d = 0; d < 32; d++) hbuf[d] = __float2half(acc[d]);
    __half* dst = g_ae + ((size_t)(b * NTOK + i)) * DIMC + hoff;
#pragma unroll
    for (int j = 0; j < 4; j++)
        *(uint4*)&dst[j * 8] = ((const uint4*)hbuf)[j];
}

// ---------------- launch ----------------------------------------------------
extern "C" void kernel_launch(void* const* d_in, const int* in_sizes, int n_in,
                              void* d_out, int out_size)
{
    const float* x       = (const float*)d_in[0];
    const float* qkv_w   = (const float*)d_in[1];
    const float* qkv_b   = (const float*)d_in[2];
    const float* pos_enc = (const float*)d_in[3];
    const float* dwc_w   = (const float*)d_in[4];
    const float* dwc_b   = (const float*)d_in[5];
    const float* proj_w  = (const float*)d_in[6];
    const float* proj_b  = (const float*)d_in[7];
    float* out = (float*)d_out;

    cudaFuncSetAttribute(attn_kernel,
                         cudaFuncAttributeMaxDynamicSharedMemorySize, AT_BYTES);
    cudaFuncSetAttribute(gemm_f16<0>,
                         cudaFuncAttributeMaxDynamicSharedMemorySize, GEMM_SMEM);
    cudaFuncSetAttribute(gemm_f16<1>,
                         cudaFuncAttributeMaxDynamicSharedMemorySize, GEMM_SMEM);

    __half* ae; cudaGetSymbolAddress((void**)&ae, g_ae);
    __half* we; cudaGetSymbolAddress((void**)&we, g_we);
    __half* pe; cudaGetSymbolAddress((void**)&pe, g_pe);

    // 0) conversions: x, qkv_w, proj_w -> fp16 (elementwise)
    {
        int nq = MTOT * DIMC / 4;
        cvt_half<<<(nq + 255) / 256, 256>>>(x, ae, nq);
        int nw = NQKV * DIMC / 4;
        cvt_half<<<(nw + 255) / 256, 256>>>(qkv_w, we, nw);
        int np = DIMC * DIMC / 4;
        cvt_half<<<(np + 255) / 256, 256>>>(proj_w, pe, np);
    }

    // 1) qkv GEMM (fp16 TC) -> g_qkv fp16 [m][1152], coalesced
    gemm_f16<0><<<dim3(NQKV / 128, MTOT / 128), 256, GEMM_SMEM>>>(
        ae, we, qkv_b, pos_enc, nullptr);

    // 2) fused linear attention + depthwise conv -> y_f16 (reuses g_ae)
    attn_kernel<<<BHTOT, 256, AT_BYTES>>>(dwc_w, dwc_b);

    // 3) proj GEMM (fp16 TC) -> out
    gemm_f16<1><<<dim3(DIMC / 128, MTOT / 128), 256, GEMM_SMEM>>>(
        ae, pe, proj_b, nullptr, out);
}